// round 8
// baseline (speedup 1.0000x reference)
#include <cuda_runtime.h>
#include <cuda_bf16.h>
#include <math.h>
#include <float.h>

#define BGR   32
#define NPER0 1024
#define N0    (BGR * NPER0)
#define HID   128
#define NE    524288
#define EPG   (NE / BGR)     // per-graph edge region (16384)
#define KK1   512
#define KK2   256
#define KK3   128
#define NC    10
#define MAXDEG 128
#define N1    (BGR * KK1)
#define N2    (BGR * KK2)

// ---------------- scratch (static device memory) ----------------
__device__ __align__(16) float g_X[N0 * HID];
__device__ __align__(16) float g_X2[N0 * HID];
__device__ __align__(16) float g_XS[N0 * HID];
__device__ float g_dinv[N0];
__device__ float g_catd[N0];
__device__ int   g_cnt0[N0];
__device__ int   g_cnt1[N1];
__device__ int   g_cnt2[N2];
__device__ int   g_csr[N0 * MAXDEG];
__device__ int   g_srcA[NE], g_dstA[NE];   // per-graph regions of EPG
__device__ int   g_srcB[NE], g_dstB[NE];
__device__ int   g_ecntA[BGR], g_ecntB[BGR];
__device__ float g_r[BGR * 2 * HID];

static inline int ceil_div(int a, int b) { return (a + b - 1) / b; }

__device__ __forceinline__ unsigned f2u_ord(float f) {
    unsigned u = __float_as_uint(f);
    return (u & 0x80000000u) ? ~u : (u | 0x80000000u);
}
__device__ __forceinline__ float u2f_ord(unsigned m) {
    unsigned u = (m & 0x80000000u) ? (m & 0x7FFFFFFFu) : ~m;
    return __uint_as_float(u);
}

// ---------------- kernels ----------------
__global__ void k_init(int* c0, int* c1, int* c2) {
    int i = blockIdx.x * blockDim.x + threadIdx.x;
    if (i < N0) c0[i] = 0;
    if (i < N1) c1[i] = 0;
    if (i < N2) c2[i] = 0;
}

// build fixed-stride CSR. If ecntg != null, edges live in per-graph regions of
// EPG with ecntg[g] valid entries; else linear list of cntv edges.
__global__ void k_build(const int* __restrict__ src, const int* __restrict__ dst,
                        int* __restrict__ cnt, int* __restrict__ csr,
                        const int* __restrict__ ecntg, int cntv) {
    int e = blockIdx.x * blockDim.x + threadIdx.x;
    if (e >= cntv) return;
    if (ecntg) {
        int g = e / EPG, i = e - g * EPG;
        if (i >= ecntg[g]) return;
    }
    int d = dst[e];
    int slot = atomicAdd(&cnt[d], 1);
    if (slot < MAXDEG) csr[d * MAXDEG + slot] = src[e];
}

// Xs = Xin * dinv[node]; also writes dinv (fused, removes k_dinv)
__global__ void k_scale(const float* __restrict__ Xin, const int* __restrict__ cnt,
                        float* __restrict__ dinv, float* __restrict__ Xs, int n) {
    int i = blockIdx.x * blockDim.x + threadIdx.x;
    if (i >= n * 32) return;
    int node = i >> 5;
    float d = rsqrtf((float)(cnt[node] + 1));
    if ((i & 31) == 0) dinv[node] = d;
    float4 v = ((const float4*)Xin)[i];
    ((float4*)Xs)[i] = make_float4(v.x * d, v.y * d, v.z * d, v.w * d);
}

// Warp-per-node fused agg + per-head projection + relu + attention (see R6).
#define NPB3 32
__global__ void k_aggXP(const float* __restrict__ Xs, const int* __restrict__ cnt,
                        const int* __restrict__ csr, const float* __restrict__ dinv,
                        const float* __restrict__ W, const float* __restrict__ b,
                        const float* __restrict__ A, const float* __restrict__ psW,
                        float* __restrict__ Xout, float* __restrict__ catd, int n) {
    __shared__ float sW[4096];
    int t = threadIdx.x;
    #pragma unroll
    for (int i = 0; i < 16; i++) sW[i * 256 + t] = W[i * 256 + t];
    __syncthreads();
    int w = t >> 5, lane = t & 31;
    int head = lane >> 3;
    int baseLane = head << 3;
    int oct = lane & 7;
    const float4* Xs4 = (const float4*)Xs;
    float4 b4  = ((const float4*)b)[lane];
    float4 A4  = ((const float4*)A)[lane];
    float4 pw4 = ((const float4*)psW)[lane];
    const float* whBase = sW + head * 1024 + oct * 4;
    int base = blockIdx.x * NPB3;
    #pragma unroll 1
    for (int it = 0; it < NPB3 / 8; it++) {
        int node = base + it * 8 + w;
        if (node >= n) break;
        int deg = cnt[node];
        float di = dinv[node];
        const int* row = csr + (size_t)node * MAXDEG;
        float4 acc = Xs4[(size_t)node * 32 + lane];
        int j = 0;
        for (; j + 8 <= deg; j += 8) {
            int4 sa = *(const int4*)(row + j);
            int4 sb = *(const int4*)(row + j + 4);
            float4 v0 = Xs4[(size_t)sa.x * 32 + lane];
            float4 v1 = Xs4[(size_t)sa.y * 32 + lane];
            float4 v2 = Xs4[(size_t)sa.z * 32 + lane];
            float4 v3 = Xs4[(size_t)sa.w * 32 + lane];
            float4 v4 = Xs4[(size_t)sb.x * 32 + lane];
            float4 v5 = Xs4[(size_t)sb.y * 32 + lane];
            float4 v6 = Xs4[(size_t)sb.z * 32 + lane];
            float4 v7 = Xs4[(size_t)sb.w * 32 + lane];
            acc.x += ((v0.x + v1.x) + (v2.x + v3.x)) + ((v4.x + v5.x) + (v6.x + v7.x));
            acc.y += ((v0.y + v1.y) + (v2.y + v3.y)) + ((v4.y + v5.y) + (v6.y + v7.y));
            acc.z += ((v0.z + v1.z) + (v2.z + v3.z)) + ((v4.z + v5.z) + (v6.z + v7.z));
            acc.w += ((v0.w + v1.w) + (v2.w + v3.w)) + ((v4.w + v5.w) + (v6.w + v7.w));
        }
        for (; j + 4 <= deg; j += 4) {
            int4 s4 = *(const int4*)(row + j);
            float4 v0 = Xs4[(size_t)s4.x * 32 + lane];
            float4 v1 = Xs4[(size_t)s4.y * 32 + lane];
            float4 v2 = Xs4[(size_t)s4.z * 32 + lane];
            float4 v3 = Xs4[(size_t)s4.w * 32 + lane];
            acc.x += (v0.x + v1.x) + (v2.x + v3.x);
            acc.y += (v0.y + v1.y) + (v2.y + v3.y);
            acc.z += (v0.z + v1.z) + (v2.z + v3.z);
            acc.w += (v0.w + v1.w) + (v2.w + v3.w);
        }
        for (; j < deg; j++) {
            float4 v0 = Xs4[(size_t)row[j] * 32 + lane];
            acc.x += v0.x; acc.y += v0.y; acc.z += v0.z; acc.w += v0.w;
        }
        float4 v = make_float4(acc.x * di, acc.y * di, acc.z * di, acc.w * di);
        float4 o = make_float4(0.f, 0.f, 0.f, 0.f);
        #pragma unroll
        for (int i = 0; i < 8; i++) {
            int sl = baseLane + i;
            float vv0 = __shfl_sync(0xffffffffu, v.x, sl);
            float vv1 = __shfl_sync(0xffffffffu, v.y, sl);
            float vv2 = __shfl_sync(0xffffffffu, v.z, sl);
            float vv3 = __shfl_sync(0xffffffffu, v.w, sl);
            const float* wp = whBase + (i * 4) * 32;
            float4 w0 = *(const float4*)(wp);
            float4 w1 = *(const float4*)(wp + 32);
            float4 w2 = *(const float4*)(wp + 64);
            float4 w3 = *(const float4*)(wp + 96);
            o.x = fmaf(vv0, w0.x, o.x); o.y = fmaf(vv0, w0.y, o.y);
            o.z = fmaf(vv0, w0.z, o.z); o.w = fmaf(vv0, w0.w, o.w);
            o.x = fmaf(vv1, w1.x, o.x); o.y = fmaf(vv1, w1.y, o.y);
            o.z = fmaf(vv1, w1.z, o.z); o.w = fmaf(vv1, w1.w, o.w);
            o.x = fmaf(vv2, w2.x, o.x); o.y = fmaf(vv2, w2.y, o.y);
            o.z = fmaf(vv2, w2.z, o.z); o.w = fmaf(vv2, w2.w, o.w);
            o.x = fmaf(vv3, w3.x, o.x); o.y = fmaf(vv3, w3.y, o.y);
            o.z = fmaf(vv3, w3.z, o.z); o.w = fmaf(vv3, w3.w, o.w);
        }
        o.x = fmaxf(o.x + b4.x, 0.f);
        o.y = fmaxf(o.y + b4.y, 0.f);
        o.z = fmaxf(o.z + b4.z, 0.f);
        o.w = fmaxf(o.w + b4.w, 0.f);
        ((float4*)Xout)[(size_t)node * 32 + lane] = o;
        float att = o.x * A4.x + o.y * A4.y + o.z * A4.z + o.w * A4.w;
        att += __shfl_xor_sync(0xffffffffu, att, 1);
        att += __shfl_xor_sync(0xffffffffu, att, 2);
        att += __shfl_xor_sync(0xffffffffu, att, 4);
        float cp = att * (o.x * pw4.x + o.y * pw4.y + o.z * pw4.z + o.w * pw4.w);
        #pragma unroll
        for (int ofs = 16; ofs > 0; ofs >>= 1)
            cp += __shfl_xor_sync(0xffffffffu, cp, ofs);
        if (lane == 0) catd[node] = cp * di;
    }
}

// Fused per-graph: score gather, u64 bitonic sort, pool+readout, AND in-block
// edge compaction for the next stage (edges are graph-contiguous: stage-1 by
// construction, later stages via per-graph EPG regions).
__global__ void k_select(const float* __restrict__ catd, const float* __restrict__ dinv,
                         const int* __restrict__ cnt, const int* __restrict__ csr,
                         const float* __restrict__ psb, const float* __restrict__ Xmid,
                         float* __restrict__ Xpool, float* __restrict__ r,
                         int nper, int k, int accum,
                         const int* __restrict__ esrc, const int* __restrict__ edst,
                         const int* __restrict__ ecntgIn,
                         int* __restrict__ srcO, int* __restrict__ dstO,
                         int* __restrict__ ecntgOut) {
    __shared__ unsigned long long skey[1024];
    __shared__ float scd[1024];
    __shared__ int   snmap[1024];
    __shared__ float smx[512], ssm[512];
    __shared__ int scnt;
    int g = blockIdx.x, t = threadIdx.x;   // 512 threads
    int base = g * nper;
    if (t == 0) scnt = 0;
    for (int i = t; i < nper; i += 512) {
        scd[i] = catd[base + i];
        snmap[i] = -1;
    }
    __syncthreads();
    float pb = psb[0];
    for (int i = t; i < nper; i += 512) {
        int node = base + i;
        int deg = cnt[node];
        const int* row = csr + (size_t)node * MAXDEG;
        float din = dinv[node];
        float s2 = scd[i] * din;
        for (int j = 0; j < deg; j++) s2 += scd[row[j] - base];
        float sc = fmaf(s2, din, pb);
        skey[i] = ((unsigned long long)f2u_ord(sc) << 32) | (unsigned)(~i);
    }
    __syncthreads();
    for (int ks = 2; ks <= nper; ks <<= 1) {
        for (int j = ks >> 1; j > 0; j >>= 1) {
            for (int i = t; i < nper; i += 512) {
                int ixj = i ^ j;
                if (ixj > i) {
                    unsigned long long ka = skey[i], kb = skey[ixj];
                    bool dirUp = ((i & ks) == 0);
                    bool sw = dirUp ? (ka < kb) : (ka > kb);
                    if (sw) { skey[i] = kb; skey[ixj] = ka; }
                }
            }
            __syncthreads();
        }
    }
    for (int jj = t; jj < k; jj += 512)
        snmap[(int)(~(unsigned)skey[jj])] = g * k + jj;
    __syncthreads();
    // pool + readout
    int f = t & 127, c = t >> 7;
    float mx = -FLT_MAX, sm = 0.f;
    for (int j = c; j < k; j += 4) {
        unsigned long long key = skey[j];
        int orig = base + (int)(~(unsigned)key);
        float tv = tanhf(u2f_ord((unsigned)(key >> 32)));
        float v = Xmid[(size_t)orig * 128 + f] * tv;
        Xpool[(size_t)(g * k + j) * 128 + f] = v;
        mx = fmaxf(mx, v);
        sm += v;
    }
    smx[t] = mx; ssm[t] = sm;
    __syncthreads();
    if (c == 0) {
        #pragma unroll
        for (int cc = 1; cc < 4; cc++) {
            mx = fmaxf(mx, smx[cc * 128 + f]);
            sm += ssm[cc * 128 + f];
        }
        float o1 = mx, o2 = sm / (float)k;
        if (accum) { r[g * 256 + f] += o1; r[g * 256 + 128 + f] += o2; }
        else       { r[g * 256 + f]  = o1; r[g * 256 + 128 + f]  = o2; }
    }
    // in-block edge compaction for next stage
    if (srcO) {
        int ecount = ecntgIn ? ecntgIn[g] : EPG;
        const int* es = esrc + g * EPG;
        const int* ed = edst + g * EPG;
        int lane = t & 31;
        for (int i = t; i < ((ecount + 511) & ~511); i += 512) {
            int ns = -1, nd = -1;
            bool keep = false;
            if (i < ecount) {
                ns = snmap[es[i] - base];
                nd = snmap[ed[i] - base];
                keep = (ns >= 0 && nd >= 0);
            }
            unsigned m = __ballot_sync(0xffffffffu, keep);
            if (m) {
                int cnt2 = __popc(m);
                int leader = __ffs(m) - 1;
                int bp = 0;
                if (lane == leader) bp = atomicAdd(&scnt, cnt2);
                bp = __shfl_sync(0xffffffffu, bp, leader);
                if (keep) {
                    int off = __popc(m & ((1u << lane) - 1u));
                    srcO[g * EPG + bp + off] = ns;
                    dstO[g * EPG + bp + off] = nd;
                }
            }
        }
        __syncthreads();
        if (t == 0) ecntgOut[g] = scnt;
    }
}

__global__ void k_mlp(const float* __restrict__ r,
                      const float* __restrict__ l1W, const float* __restrict__ l1b,
                      const float* __restrict__ l2W, const float* __restrict__ l2b,
                      const float* __restrict__ l3W, const float* __restrict__ l3b,
                      float* __restrict__ out) {
    __shared__ float z0[256], z1[128], z2[64], z3[16];
    __shared__ float red2[2];
    int g = blockIdx.x, t = threadIdx.x;
    z0[t] = r[g * 256 + t];
    z0[t + 128] = r[g * 256 + 128 + t];
    __syncthreads();
    {
        float acc = l1b[t];
        for (int i = 0; i < 256; i++) acc = fmaf(z0[i], l1W[i * 128 + t], acc);
        z1[t] = fmaxf(acc, 0.f);
    }
    __syncthreads();
    if (t < 64) {
        float acc = l2b[t];
        for (int i = 0; i < 128; i++) acc = fmaf(z1[i], l2W[i * 64 + t], acc);
        z2[t] = fmaxf(acc, 0.f);
    }
    __syncthreads();
    if (t < NC) {
        float acc = l3b[t];
        for (int i = 0; i < 64; i++) acc = fmaf(z2[i], l3W[i * NC + t], acc);
        z3[t] = acc;
    }
    __syncthreads();
    if (t == 0) {
        float m = -FLT_MAX;
        for (int c = 0; c < NC; c++) m = fmaxf(m, z3[c]);
        float s = 0.f;
        for (int c = 0; c < NC; c++) s += expf(z3[c] - m);
        red2[0] = m; red2[1] = logf(s);
    }
    __syncthreads();
    if (t < NC) out[g * NC + t] = z3[t] - red2[0] - red2[1];
}

// ---------------- host side ----------------
struct Ptrs {
    float *X, *X2, *XS, *dinv, *catd, *r;
    int *cnt0, *cnt1, *cnt2, *csr;
    int *srcA, *dstA, *srcB, *dstB, *ecntA, *ecntB;
};

static void run_stage(const Ptrs& P, const float* Xin, int* cnt, int n, int k,
                      const int* src, const int* dst, const int* ecntgIn,
                      const float* W, const float* b, const float* A,
                      const float* psW, const float* psb,
                      float* Xpool, int accum,
                      int* srcO, int* dstO, int* ecntgOut) {
    int nper = n / BGR;
    k_build<<<ceil_div(NE, 256), 256>>>(src, dst, cnt, P.csr, ecntgIn, NE);
    k_scale<<<ceil_div(n * 32, 256), 256>>>(Xin, cnt, P.dinv, P.XS, n);
    k_aggXP<<<ceil_div(n, NPB3), 256>>>(P.XS, cnt, P.csr, P.dinv,
                                        W, b, A, psW, P.X, P.catd, n);
    k_select<<<BGR, 512>>>(P.catd, P.dinv, cnt, P.csr, psb, P.X,
                           Xpool, P.r, nper, k, accum,
                           src, dst, ecntgIn, srcO, dstO, ecntgOut);
}

extern "C" void kernel_launch(void* const* d_in, const int* in_sizes, int n_in,
                              void* d_out, int out_size) {
    const float* x   = (const float*)d_in[0];
    const int*   src = (const int*)d_in[1];
    const int*   dst = (const int*)d_in[2];
    const float* W1 = (const float*)d_in[3];
    const float* b1 = (const float*)d_in[4];
    const float* A1 = (const float*)d_in[5];
    const float* ps1W = (const float*)d_in[6];
    const float* ps1b = (const float*)d_in[7];
    const float* W2 = (const float*)d_in[8];
    const float* b2 = (const float*)d_in[9];
    const float* A2 = (const float*)d_in[10];
    const float* ps2W = (const float*)d_in[11];
    const float* ps2b = (const float*)d_in[12];
    const float* W3 = (const float*)d_in[13];
    const float* b3 = (const float*)d_in[14];
    const float* A3 = (const float*)d_in[15];
    const float* ps3W = (const float*)d_in[16];
    const float* ps3b = (const float*)d_in[17];
    const float* l1W = (const float*)d_in[18];
    const float* l1b = (const float*)d_in[19];
    const float* l2W = (const float*)d_in[20];
    const float* l2b = (const float*)d_in[21];
    const float* l3W = (const float*)d_in[22];
    const float* l3b = (const float*)d_in[23];
    float* out = (float*)d_out;

    Ptrs P;
    cudaGetSymbolAddress((void**)&P.X, g_X);
    cudaGetSymbolAddress((void**)&P.X2, g_X2);
    cudaGetSymbolAddress((void**)&P.XS, g_XS);
    cudaGetSymbolAddress((void**)&P.dinv, g_dinv);
    cudaGetSymbolAddress((void**)&P.catd, g_catd);
    cudaGetSymbolAddress((void**)&P.r, g_r);
    cudaGetSymbolAddress((void**)&P.cnt0, g_cnt0);
    cudaGetSymbolAddress((void**)&P.cnt1, g_cnt1);
    cudaGetSymbolAddress((void**)&P.cnt2, g_cnt2);
    cudaGetSymbolAddress((void**)&P.csr, g_csr);
    cudaGetSymbolAddress((void**)&P.srcA, g_srcA);
    cudaGetSymbolAddress((void**)&P.dstA, g_dstA);
    cudaGetSymbolAddress((void**)&P.srcB, g_srcB);
    cudaGetSymbolAddress((void**)&P.dstB, g_dstB);
    cudaGetSymbolAddress((void**)&P.ecntA, g_ecntA);
    cudaGetSymbolAddress((void**)&P.ecntB, g_ecntB);

    k_init<<<ceil_div(N0, 256), 256>>>(P.cnt0, P.cnt1, P.cnt2);

    // stage 1: input edges are graph-contiguous (EPG per graph)
    run_stage(P, x, P.cnt0, N0, KK1, src, dst, nullptr,
              W1, b1, A1, ps1W, ps1b, P.X2, 0,
              P.srcA, P.dstA, P.ecntA);
    // stage 2
    run_stage(P, P.X2, P.cnt1, N1, KK2, P.srcA, P.dstA, P.ecntA,
              W2, b2, A2, ps2W, ps2b, P.X2, 1,
              P.srcB, P.dstB, P.ecntB);
    // stage 3 (no compaction output)
    run_stage(P, P.X2, P.cnt2, N2, KK3, P.srcB, P.dstB, P.ecntB,
              W3, b3, A3, ps3W, ps3b, P.X2, 1,
              nullptr, nullptr, nullptr);

    k_mlp<<<BGR, 128>>>(P.r, l1W, l1b, l2W, l2b, l3W, l3b, out);
}

// round 9
// speedup vs baseline: 1.0993x; 1.0993x over previous
#include <cuda_runtime.h>
#include <cuda_bf16.h>
#include <math.h>
#include <float.h>

#define BGR   32
#define NPER0 1024
#define N0    (BGR * NPER0)
#define HID   128
#define NE    524288
#define KK1   512
#define KK2   256
#define KK3   128
#define NC    10
#define MAXDEG 128
#define N1    (BGR * KK1)
#define N2    (BGR * KK2)

// ---------------- scratch (static device memory) ----------------
__device__ __align__(16) float g_X[N0 * HID];
__device__ __align__(16) float g_X2[N0 * HID];
__device__ __align__(16) float g_XS[N0 * HID];
__device__ float g_dinv[N0];
__device__ float g_catd[N0];
__device__ int   g_cnt0[N0];
__device__ int   g_cnt1[N1];
__device__ int   g_cnt2[N2];
__device__ int   g_csrA[N0 * MAXDEG];   // stage 1 CSR (and stage 3, rows < N2)
__device__ int   g_csrB[N1 * MAXDEG];   // stage 2 CSR
__device__ float g_r[BGR * 2 * HID];

static inline int ceil_div(int a, int b) { return (a + b - 1) / b; }

__device__ __forceinline__ unsigned f2u_ord(float f) {
    unsigned u = __float_as_uint(f);
    return (u & 0x80000000u) ? ~u : (u | 0x80000000u);
}
__device__ __forceinline__ float u2f_ord(unsigned m) {
    unsigned u = (m & 0x80000000u) ? (m & 0x7FFFFFFFu) : ~m;
    return __uint_as_float(u);
}

// ---------------- kernels ----------------
__global__ void k_init(int* c0) {
    int i = blockIdx.x * blockDim.x + threadIdx.x;
    if (i < N0) c0[i] = 0;
}

// stage-1 CSR build from the input edge list
__global__ void k_build(const int* __restrict__ src, const int* __restrict__ dst,
                        int* __restrict__ cnt, int* __restrict__ csr) {
    int e = blockIdx.x * blockDim.x + threadIdx.x;
    if (e >= NE) return;
    int d = dst[e];
    int slot = atomicAdd(&cnt[d], 1);
    if (slot < MAXDEG) csr[d * MAXDEG + slot] = src[e];
}

// Xs = Xin * dinv[node]; also writes dinv
__global__ void k_scale(const float* __restrict__ Xin, const int* __restrict__ cnt,
                        float* __restrict__ dinv, float* __restrict__ Xs, int n) {
    int i = blockIdx.x * blockDim.x + threadIdx.x;
    if (i >= n * 32) return;
    int node = i >> 5;
    float d = rsqrtf((float)(cnt[node] + 1));
    if ((i & 31) == 0) dinv[node] = d;
    float4 v = ((const float4*)Xin)[i];
    ((float4*)Xs)[i] = make_float4(v.x * d, v.y * d, v.z * d, v.w * d);
}

// Warp-per-node fused agg + per-head projection + relu + attention (R6/R7 body).
#define NPB3 32
__global__ void __launch_bounds__(256) k_aggXP(
        const float* __restrict__ Xs, const int* __restrict__ cnt,
        const int* __restrict__ csr, const float* __restrict__ dinv,
        const float* __restrict__ W, const float* __restrict__ b,
        const float* __restrict__ A, const float* __restrict__ psW,
        float* __restrict__ Xout, float* __restrict__ catd, int n) {
    __shared__ float sW[4096];
    int t = threadIdx.x;
    #pragma unroll
    for (int i = 0; i < 16; i++) sW[i * 256 + t] = W[i * 256 + t];
    __syncthreads();
    int w = t >> 5, lane = t & 31;
    int head = lane >> 3;
    int baseLane = head << 3;
    int oct = lane & 7;
    const float4* Xs4 = (const float4*)Xs;
    float4 b4  = ((const float4*)b)[lane];
    float4 A4  = ((const float4*)A)[lane];
    float4 pw4 = ((const float4*)psW)[lane];
    const float* whBase = sW + head * 1024 + oct * 4;
    int base = blockIdx.x * NPB3;
    #pragma unroll 1
    for (int it = 0; it < NPB3 / 8; it++) {
        int node = base + it * 8 + w;
        if (node >= n) break;
        int deg = cnt[node];
        float di = dinv[node];
        const int* row = csr + (size_t)node * MAXDEG;
        float4 acc = Xs4[(size_t)node * 32 + lane];
        int j = 0;
        for (; j + 4 <= deg; j += 4) {
            int4 s4 = *(const int4*)(row + j);
            float4 v0 = Xs4[(size_t)s4.x * 32 + lane];
            float4 v1 = Xs4[(size_t)s4.y * 32 + lane];
            float4 v2 = Xs4[(size_t)s4.z * 32 + lane];
            float4 v3 = Xs4[(size_t)s4.w * 32 + lane];
            acc.x += (v0.x + v1.x) + (v2.x + v3.x);
            acc.y += (v0.y + v1.y) + (v2.y + v3.y);
            acc.z += (v0.z + v1.z) + (v2.z + v3.z);
            acc.w += (v0.w + v1.w) + (v2.w + v3.w);
        }
        for (; j < deg; j++) {
            float4 v0 = Xs4[(size_t)row[j] * 32 + lane];
            acc.x += v0.x; acc.y += v0.y; acc.z += v0.z; acc.w += v0.w;
        }
        float4 v = make_float4(acc.x * di, acc.y * di, acc.z * di, acc.w * di);
        float4 o = make_float4(0.f, 0.f, 0.f, 0.f);
        #pragma unroll
        for (int i = 0; i < 8; i++) {
            int sl = baseLane + i;
            float vv0 = __shfl_sync(0xffffffffu, v.x, sl);
            float vv1 = __shfl_sync(0xffffffffu, v.y, sl);
            float vv2 = __shfl_sync(0xffffffffu, v.z, sl);
            float vv3 = __shfl_sync(0xffffffffu, v.w, sl);
            const float* wp = whBase + (i * 4) * 32;
            float4 w0 = *(const float4*)(wp);
            float4 w1 = *(const float4*)(wp + 32);
            float4 w2 = *(const float4*)(wp + 64);
            float4 w3 = *(const float4*)(wp + 96);
            o.x = fmaf(vv0, w0.x, o.x); o.y = fmaf(vv0, w0.y, o.y);
            o.z = fmaf(vv0, w0.z, o.z); o.w = fmaf(vv0, w0.w, o.w);
            o.x = fmaf(vv1, w1.x, o.x); o.y = fmaf(vv1, w1.y, o.y);
            o.z = fmaf(vv1, w1.z, o.z); o.w = fmaf(vv1, w1.w, o.w);
            o.x = fmaf(vv2, w2.x, o.x); o.y = fmaf(vv2, w2.y, o.y);
            o.z = fmaf(vv2, w2.z, o.z); o.w = fmaf(vv2, w2.w, o.w);
            o.x = fmaf(vv3, w3.x, o.x); o.y = fmaf(vv3, w3.y, o.y);
            o.z = fmaf(vv3, w3.z, o.z); o.w = fmaf(vv3, w3.w, o.w);
        }
        o.x = fmaxf(o.x + b4.x, 0.f);
        o.y = fmaxf(o.y + b4.y, 0.f);
        o.z = fmaxf(o.z + b4.z, 0.f);
        o.w = fmaxf(o.w + b4.w, 0.f);
        ((float4*)Xout)[(size_t)node * 32 + lane] = o;
        float att = o.x * A4.x + o.y * A4.y + o.z * A4.z + o.w * A4.w;
        att += __shfl_xor_sync(0xffffffffu, att, 1);
        att += __shfl_xor_sync(0xffffffffu, att, 2);
        att += __shfl_xor_sync(0xffffffffu, att, 4);
        float cp = att * (o.x * pw4.x + o.y * pw4.y + o.z * pw4.z + o.w * pw4.w);
        #pragma unroll
        for (int ofs = 16; ofs > 0; ofs >>= 1)
            cp += __shfl_xor_sync(0xffffffffu, cp, ofs);
        if (lane == 0) catd[node] = cp * di;
    }
}

// Fused per-graph: score gather, u64 bitonic sort, pool+readout, and CSR->CSR
// compaction for the next stage (thread-per-dst-row, zero atomics).
__global__ void k_select(const float* __restrict__ catd, const float* __restrict__ dinv,
                         const int* __restrict__ cnt, const int* __restrict__ csrIn,
                         const float* __restrict__ psb, const float* __restrict__ Xmid,
                         float* __restrict__ Xpool, float* __restrict__ r,
                         int nper, int k, int accum,
                         int* __restrict__ csrOut, int* __restrict__ cntOut) {
    __shared__ unsigned long long skey[1024];
    __shared__ float scd[1024];
    __shared__ int   snmap[1024];
    __shared__ float smx[512], ssm[512];
    int g = blockIdx.x, t = threadIdx.x;   // 512 threads
    int base = g * nper;
    for (int i = t; i < nper; i += 512) {
        scd[i] = catd[base + i];
        snmap[i] = -1;
    }
    __syncthreads();
    float pb = psb[0];
    for (int i = t; i < nper; i += 512) {
        int node = base + i;
        int deg = cnt[node];
        const int* row = csrIn + (size_t)node * MAXDEG;
        float din = dinv[node];
        float s2 = scd[i] * din;
        for (int j = 0; j < deg; j++) s2 += scd[row[j] - base];
        float sc = fmaf(s2, din, pb);
        skey[i] = ((unsigned long long)f2u_ord(sc) << 32) | (unsigned)(~i);
    }
    __syncthreads();
    for (int ks = 2; ks <= nper; ks <<= 1) {
        for (int j = ks >> 1; j > 0; j >>= 1) {
            for (int i = t; i < nper; i += 512) {
                int ixj = i ^ j;
                if (ixj > i) {
                    unsigned long long ka = skey[i], kb = skey[ixj];
                    bool dirUp = ((i & ks) == 0);
                    bool sw = dirUp ? (ka < kb) : (ka > kb);
                    if (sw) { skey[i] = kb; skey[ixj] = ka; }
                }
            }
            __syncthreads();
        }
    }
    for (int jj = t; jj < k; jj += 512)
        snmap[(int)(~(unsigned)skey[jj])] = g * k + jj;
    __syncthreads();
    // pool + readout
    int f = t & 127, c = t >> 7;
    float mx = -FLT_MAX, sm = 0.f;
    for (int j = c; j < k; j += 4) {
        unsigned long long key = skey[j];
        int orig = base + (int)(~(unsigned)key);
        float tv = tanhf(u2f_ord((unsigned)(key >> 32)));
        float v = Xmid[(size_t)orig * 128 + f] * tv;
        Xpool[(size_t)(g * k + j) * 128 + f] = v;
        mx = fmaxf(mx, v);
        sm += v;
    }
    smx[t] = mx; ssm[t] = sm;
    __syncthreads();
    if (c == 0) {
        #pragma unroll
        for (int cc = 1; cc < 4; cc++) {
            mx = fmaxf(mx, smx[cc * 128 + f]);
            sm += ssm[cc * 128 + f];
        }
        float o1 = mx, o2 = sm / (float)k;
        if (accum) { r[g * 256 + f] += o1; r[g * 256 + 128 + f] += o2; }
        else       { r[g * 256 + f]  = o1; r[g * 256 + 128 + f]  = o2; }
    }
    // CSR -> CSR compaction: thread owns a dst row; local cursor, no atomics.
    if (csrOut) {
        for (int i = t; i < nper; i += 512) {
            int nm = snmap[i];
            if (nm < 0) continue;
            int node = base + i;
            int deg = cnt[node];
            const int* row = csrIn + (size_t)node * MAXDEG;
            int* orow = csrOut + (size_t)nm * MAXDEG;
            int cct = 0;
            for (int j = 0; j < deg; j++) {
                int m2 = snmap[row[j] - base];
                if (m2 >= 0) orow[cct++] = m2;
            }
            cntOut[nm] = cct;
        }
    }
}

__global__ void k_mlp(const float* __restrict__ r,
                      const float* __restrict__ l1W, const float* __restrict__ l1b,
                      const float* __restrict__ l2W, const float* __restrict__ l2b,
                      const float* __restrict__ l3W, const float* __restrict__ l3b,
                      float* __restrict__ out) {
    __shared__ float z0[256], z1[128], z2[64], z3[16];
    __shared__ float red2[2];
    int g = blockIdx.x, t = threadIdx.x;
    z0[t] = r[g * 256 + t];
    z0[t + 128] = r[g * 256 + 128 + t];
    __syncthreads();
    {
        float acc = l1b[t];
        for (int i = 0; i < 256; i++) acc = fmaf(z0[i], l1W[i * 128 + t], acc);
        z1[t] = fmaxf(acc, 0.f);
    }
    __syncthreads();
    if (t < 64) {
        float acc = l2b[t];
        for (int i = 0; i < 128; i++) acc = fmaf(z1[i], l2W[i * 64 + t], acc);
        z2[t] = fmaxf(acc, 0.f);
    }
    __syncthreads();
    if (t < NC) {
        float acc = l3b[t];
        for (int i = 0; i < 64; i++) acc = fmaf(z2[i], l3W[i * NC + t], acc);
        z3[t] = acc;
    }
    __syncthreads();
    if (t == 0) {
        float m = -FLT_MAX;
        for (int c = 0; c < NC; c++) m = fmaxf(m, z3[c]);
        float s = 0.f;
        for (int c = 0; c < NC; c++) s += expf(z3[c] - m);
        red2[0] = m; red2[1] = logf(s);
    }
    __syncthreads();
    if (t < NC) out[g * NC + t] = z3[t] - red2[0] - red2[1];
}

// ---------------- host side ----------------
extern "C" void kernel_launch(void* const* d_in, const int* in_sizes, int n_in,
                              void* d_out, int out_size) {
    const float* x   = (const float*)d_in[0];
    const int*   src = (const int*)d_in[1];
    const int*   dst = (const int*)d_in[2];
    const float* W1 = (const float*)d_in[3];
    const float* b1 = (const float*)d_in[4];
    const float* A1 = (const float*)d_in[5];
    const float* ps1W = (const float*)d_in[6];
    const float* ps1b = (const float*)d_in[7];
    const float* W2 = (const float*)d_in[8];
    const float* b2 = (const float*)d_in[9];
    const float* A2 = (const float*)d_in[10];
    const float* ps2W = (const float*)d_in[11];
    const float* ps2b = (const float*)d_in[12];
    const float* W3 = (const float*)d_in[13];
    const float* b3 = (const float*)d_in[14];
    const float* A3 = (const float*)d_in[15];
    const float* ps3W = (const float*)d_in[16];
    const float* ps3b = (const float*)d_in[17];
    const float* l1W = (const float*)d_in[18];
    const float* l1b = (const float*)d_in[19];
    const float* l2W = (const float*)d_in[20];
    const float* l2b = (const float*)d_in[21];
    const float* l3W = (const float*)d_in[22];
    const float* l3b = (const float*)d_in[23];
    float* out = (float*)d_out;

    float *X, *X2, *XS, *dinv, *catd, *r;
    int *cnt0, *cnt1, *cnt2, *csrA, *csrB;
    cudaGetSymbolAddress((void**)&X, g_X);
    cudaGetSymbolAddress((void**)&X2, g_X2);
    cudaGetSymbolAddress((void**)&XS, g_XS);
    cudaGetSymbolAddress((void**)&dinv, g_dinv);
    cudaGetSymbolAddress((void**)&catd, g_catd);
    cudaGetSymbolAddress((void**)&r, g_r);
    cudaGetSymbolAddress((void**)&cnt0, g_cnt0);
    cudaGetSymbolAddress((void**)&cnt1, g_cnt1);
    cudaGetSymbolAddress((void**)&cnt2, g_cnt2);
    cudaGetSymbolAddress((void**)&csrA, g_csrA);
    cudaGetSymbolAddress((void**)&csrB, g_csrB);

    k_init<<<ceil_div(N0, 256), 256>>>(cnt0);
    k_build<<<ceil_div(NE, 256), 256>>>(src, dst, cnt0, csrA);

    // stage 1
    k_scale<<<ceil_div(N0 * 32, 256), 256>>>(x, cnt0, dinv, XS, N0);
    k_aggXP<<<ceil_div(N0, NPB3), 256>>>(XS, cnt0, csrA, dinv,
                                         W1, b1, A1, ps1W, X, catd, N0);
    k_select<<<BGR, 512>>>(catd, dinv, cnt0, csrA, ps1b, X,
                           X2, r, NPER0, KK1, 0, csrB, cnt1);
    // stage 2
    k_scale<<<ceil_div(N1 * 32, 256), 256>>>(X2, cnt1, dinv, XS, N1);
    k_aggXP<<<ceil_div(N1, NPB3), 256>>>(XS, cnt1, csrB, dinv,
                                         W2, b2, A2, ps2W, X, catd, N1);
    k_select<<<BGR, 512>>>(catd, dinv, cnt1, csrB, ps2b, X,
                           X2, r, KK1, KK2, 1, csrA, cnt2);
    // stage 3
    k_scale<<<ceil_div(N2 * 32, 256), 256>>>(X2, cnt2, dinv, XS, N2);
    k_aggXP<<<ceil_div(N2, NPB3), 256>>>(XS, cnt2, csrA, dinv,
                                         W3, b3, A3, ps3W, X, catd, N2);
    k_select<<<BGR, 512>>>(catd, dinv, cnt2, csrA, ps3b, X,
                           X2, r, KK2, KK3, 1, nullptr, nullptr);

    k_mlp<<<BGR, 128>>>(r, l1W, l1b, l2W, l2b, l3W, l3b, out);
}

// round 10
// speedup vs baseline: 1.1507x; 1.0467x over previous
#include <cuda_runtime.h>
#include <cuda_bf16.h>
#include <math.h>
#include <float.h>

#define BGR   32
#define NPER0 1024
#define N0    (BGR * NPER0)
#define HID   128
#define NE    524288
#define KK1   512
#define KK2   256
#define KK3   128
#define NC    10
#define MAXDEG 128
#define N1    (BGR * KK1)
#define N2    (BGR * KK2)

// ---------------- scratch (static device memory) ----------------
__device__ __align__(16) float g_X[N0 * HID];    // post-layer output
__device__ __align__(16) float g_XS[N0 * HID];   // prescaled stage input
__device__ float g_catd[N0];
__device__ int   g_cnt0[N0];     // zero-initialized at load; re-zeroed by k_mlp
__device__ int   g_cnt1[N1];
__device__ int   g_cnt2[N2];
__device__ int   g_csrA[N0 * MAXDEG];
__device__ int   g_csrB[N1 * MAXDEG];
__device__ float g_r[BGR * 2 * HID];

static inline int ceil_div(int a, int b) { return (a + b - 1) / b; }

__device__ __forceinline__ unsigned f2u_ord(float f) {
    unsigned u = __float_as_uint(f);
    return (u & 0x80000000u) ? ~u : (u | 0x80000000u);
}
__device__ __forceinline__ float u2f_ord(unsigned m) {
    unsigned u = (m & 0x80000000u) ? (m & 0x7FFFFFFFu) : ~m;
    return __uint_as_float(u);
}

// ---------------- kernels ----------------
// stage-1 CSR build from the input edge list (cnt0 must be zero on entry;
// zero-init at load + re-zeroed by k_mlp each call)
__global__ void k_build(const int* __restrict__ src, const int* __restrict__ dst,
                        int* __restrict__ cnt, int* __restrict__ csr) {
    int e = blockIdx.x * blockDim.x + threadIdx.x;
    if (e >= NE) return;
    int d = dst[e];
    int slot = atomicAdd(&cnt[d], 1);
    if (slot < MAXDEG) csr[d * MAXDEG + slot] = src[e];
}

// stage-1 prescale: XS = x * rsqrt(deg)
__global__ void k_scale(const float* __restrict__ Xin, const int* __restrict__ cnt,
                        float* __restrict__ Xs, int n) {
    int i = blockIdx.x * blockDim.x + threadIdx.x;
    if (i >= n * 32) return;
    float d = rsqrtf((float)(cnt[i >> 5] + 1));
    float4 v = ((const float4*)Xin)[i];
    ((float4*)Xs)[i] = make_float4(v.x * d, v.y * d, v.z * d, v.w * d);
}

// Warp-per-node fused agg + per-head projection + relu + attention.
#define NPB3 32
__global__ void __launch_bounds__(256) k_aggXP(
        const float* __restrict__ Xs, const int* __restrict__ cnt,
        const int* __restrict__ csr,
        const float* __restrict__ W, const float* __restrict__ b,
        const float* __restrict__ A, const float* __restrict__ psW,
        float* __restrict__ Xout, float* __restrict__ catd, int n) {
    __shared__ float sW[4096];
    int t = threadIdx.x;
    #pragma unroll
    for (int i = 0; i < 16; i++) sW[i * 256 + t] = W[i * 256 + t];
    __syncthreads();
    int w = t >> 5, lane = t & 31;
    int head = lane >> 3;
    int baseLane = head << 3;
    int oct = lane & 7;
    const float4* Xs4 = (const float4*)Xs;
    float4 b4  = ((const float4*)b)[lane];
    float4 A4  = ((const float4*)A)[lane];
    float4 pw4 = ((const float4*)psW)[lane];
    const float* whBase = sW + head * 1024 + oct * 4;
    int base = blockIdx.x * NPB3;
    #pragma unroll 1
    for (int it = 0; it < NPB3 / 8; it++) {
        int node = base + it * 8 + w;
        if (node >= n) break;
        int deg = cnt[node];
        float di = rsqrtf((float)(deg + 1));
        const int* row = csr + (size_t)node * MAXDEG;
        float4 acc = Xs4[(size_t)node * 32 + lane];
        int j = 0;
        for (; j + 4 <= deg; j += 4) {
            int4 s4 = *(const int4*)(row + j);
            float4 v0 = Xs4[(size_t)s4.x * 32 + lane];
            float4 v1 = Xs4[(size_t)s4.y * 32 + lane];
            float4 v2 = Xs4[(size_t)s4.z * 32 + lane];
            float4 v3 = Xs4[(size_t)s4.w * 32 + lane];
            acc.x += (v0.x + v1.x) + (v2.x + v3.x);
            acc.y += (v0.y + v1.y) + (v2.y + v3.y);
            acc.z += (v0.z + v1.z) + (v2.z + v3.z);
            acc.w += (v0.w + v1.w) + (v2.w + v3.w);
        }
        for (; j < deg; j++) {
            float4 v0 = Xs4[(size_t)row[j] * 32 + lane];
            acc.x += v0.x; acc.y += v0.y; acc.z += v0.z; acc.w += v0.w;
        }
        float4 v = make_float4(acc.x * di, acc.y * di, acc.z * di, acc.w * di);
        float4 o = make_float4(0.f, 0.f, 0.f, 0.f);
        #pragma unroll
        for (int i = 0; i < 8; i++) {
            int sl = baseLane + i;
            float vv0 = __shfl_sync(0xffffffffu, v.x, sl);
            float vv1 = __shfl_sync(0xffffffffu, v.y, sl);
            float vv2 = __shfl_sync(0xffffffffu, v.z, sl);
            float vv3 = __shfl_sync(0xffffffffu, v.w, sl);
            const float* wp = whBase + (i * 4) * 32;
            float4 w0 = *(const float4*)(wp);
            float4 w1 = *(const float4*)(wp + 32);
            float4 w2 = *(const float4*)(wp + 64);
            float4 w3 = *(const float4*)(wp + 96);
            o.x = fmaf(vv0, w0.x, o.x); o.y = fmaf(vv0, w0.y, o.y);
            o.z = fmaf(vv0, w0.z, o.z); o.w = fmaf(vv0, w0.w, o.w);
            o.x = fmaf(vv1, w1.x, o.x); o.y = fmaf(vv1, w1.y, o.y);
            o.z = fmaf(vv1, w1.z, o.z); o.w = fmaf(vv1, w1.w, o.w);
            o.x = fmaf(vv2, w2.x, o.x); o.y = fmaf(vv2, w2.y, o.y);
            o.z = fmaf(vv2, w2.z, o.z); o.w = fmaf(vv2, w2.w, o.w);
            o.x = fmaf(vv3, w3.x, o.x); o.y = fmaf(vv3, w3.y, o.y);
            o.z = fmaf(vv3, w3.z, o.z); o.w = fmaf(vv3, w3.w, o.w);
        }
        o.x = fmaxf(o.x + b4.x, 0.f);
        o.y = fmaxf(o.y + b4.y, 0.f);
        o.z = fmaxf(o.z + b4.z, 0.f);
        o.w = fmaxf(o.w + b4.w, 0.f);
        ((float4*)Xout)[(size_t)node * 32 + lane] = o;
        float att = o.x * A4.x + o.y * A4.y + o.z * A4.z + o.w * A4.w;
        att += __shfl_xor_sync(0xffffffffu, att, 1);
        att += __shfl_xor_sync(0xffffffffu, att, 2);
        att += __shfl_xor_sync(0xffffffffu, att, 4);
        float cp = att * (o.x * pw4.x + o.y * pw4.y + o.z * pw4.z + o.w * pw4.w);
        #pragma unroll
        for (int ofs = 16; ofs > 0; ofs >>= 1)
            cp += __shfl_xor_sync(0xffffffffu, cp, ofs);
        if (lane == 0) catd[node] = cp * di;
    }
}

// Fused per-graph: score gather + u64 bitonic sort + CSR->CSR compaction +
// pool (writes NEXT stage's prescaled XS directly) + readout.
__global__ void k_select(const float* __restrict__ catd,
                         const int* __restrict__ cnt, const int* __restrict__ csrIn,
                         const float* __restrict__ psb, const float* __restrict__ Xmid,
                         float* __restrict__ XSout, float* __restrict__ r,
                         int nper, int k, int accum,
                         int* __restrict__ csrOut, int* __restrict__ cntOut) {
    __shared__ unsigned long long skey[1024];
    __shared__ float scd[1024];
    __shared__ int   snmap[1024];
    __shared__ int   sdeg[512];
    __shared__ float smx[512], ssm[512];
    int g = blockIdx.x, t = threadIdx.x;   // 512 threads
    int base = g * nper;
    for (int i = t; i < nper; i += 512) {
        scd[i] = catd[base + i];
        snmap[i] = -1;
    }
    __syncthreads();
    float pb = psb[0];
    for (int i = t; i < nper; i += 512) {
        int node = base + i;
        int deg = cnt[node];
        const int* row = csrIn + (size_t)node * MAXDEG;
        float din = rsqrtf((float)(deg + 1));
        float s2 = scd[i] * din;
        for (int j = 0; j < deg; j++) s2 += scd[row[j] - base];
        float sc = fmaf(s2, din, pb);
        skey[i] = ((unsigned long long)f2u_ord(sc) << 32) | (unsigned)(~i);
    }
    __syncthreads();
    for (int ks = 2; ks <= nper; ks <<= 1) {
        for (int j = ks >> 1; j > 0; j >>= 1) {
            for (int i = t; i < nper; i += 512) {
                int ixj = i ^ j;
                if (ixj > i) {
                    unsigned long long ka = skey[i], kb = skey[ixj];
                    bool dirUp = ((i & ks) == 0);
                    bool sw = dirUp ? (ka < kb) : (ka > kb);
                    if (sw) { skey[i] = kb; skey[ixj] = ka; }
                }
            }
            __syncthreads();
        }
    }
    for (int jj = t; jj < k; jj += 512)
        snmap[(int)(~(unsigned)skey[jj])] = g * k + jj;
    __syncthreads();
    // CSR -> CSR compaction first (fills sdeg for the pool's prescale)
    if (csrOut) {
        for (int i = t; i < nper; i += 512) {
            int nm = snmap[i];
            if (nm < 0) continue;
            int node = base + i;
            int deg = cnt[node];
            const int* row = csrIn + (size_t)node * MAXDEG;
            int* orow = csrOut + (size_t)nm * MAXDEG;
            int cct = 0;
            for (int j = 0; j < deg; j++) {
                int m2 = snmap[row[j] - base];
                if (m2 >= 0) orow[cct++] = m2;
            }
            cntOut[nm] = cct;
            sdeg[nm - g * k] = cct;
        }
        __syncthreads();
    }
    // pool + readout; pool writes prescaled XS for next stage
    int f = t & 127, c = t >> 7;
    float mx = -FLT_MAX, sm = 0.f;
    for (int j = c; j < k; j += 4) {
        unsigned long long key = skey[j];
        int orig = base + (int)(~(unsigned)key);
        float tv = tanhf(u2f_ord((unsigned)(key >> 32)));
        float v = Xmid[(size_t)orig * 128 + f] * tv;
        if (XSout) {
            float dnext = rsqrtf((float)(sdeg[j] + 1));
            XSout[(size_t)(g * k + j) * 128 + f] = v * dnext;
        }
        mx = fmaxf(mx, v);
        sm += v;
    }
    smx[t] = mx; ssm[t] = sm;
    __syncthreads();
    if (c == 0) {
        #pragma unroll
        for (int cc = 1; cc < 4; cc++) {
            mx = fmaxf(mx, smx[cc * 128 + f]);
            sm += ssm[cc * 128 + f];
        }
        float o1 = mx, o2 = sm / (float)k;
        if (accum) { r[g * 256 + f] += o1; r[g * 256 + 128 + f] += o2; }
        else       { r[g * 256 + f]  = o1; r[g * 256 + 128 + f]  = o2; }
    }
}

__global__ void k_mlp(const float* __restrict__ r,
                      const float* __restrict__ l1W, const float* __restrict__ l1b,
                      const float* __restrict__ l2W, const float* __restrict__ l2b,
                      const float* __restrict__ l3W, const float* __restrict__ l3b,
                      float* __restrict__ out, int* __restrict__ cnt0z) {
    __shared__ float z0[256], z1[128], z2[64], z3[16];
    __shared__ float red2[2];
    int g = blockIdx.x, t = threadIdx.x;
    z0[t] = r[g * 256 + t];
    z0[t + 128] = r[g * 256 + 128 + t];
    __syncthreads();
    {
        float acc = l1b[t];
        for (int i = 0; i < 256; i++) acc = fmaf(z0[i], l1W[i * 128 + t], acc);
        z1[t] = fmaxf(acc, 0.f);
    }
    __syncthreads();
    if (t < 64) {
        float acc = l2b[t];
        for (int i = 0; i < 128; i++) acc = fmaf(z1[i], l2W[i * 64 + t], acc);
        z2[t] = fmaxf(acc, 0.f);
    }
    __syncthreads();
    if (t < NC) {
        float acc = l3b[t];
        for (int i = 0; i < 64; i++) acc = fmaf(z2[i], l3W[i * NC + t], acc);
        z3[t] = acc;
    }
    __syncthreads();
    if (t == 0) {
        float m = -FLT_MAX;
        for (int c = 0; c < NC; c++) m = fmaxf(m, z3[c]);
        float s = 0.f;
        for (int c = 0; c < NC; c++) s += expf(z3[c] - m);
        red2[0] = m; red2[1] = logf(s);
    }
    __syncthreads();
    if (t < NC) out[g * NC + t] = z3[t] - red2[0] - red2[1];
    // re-zero stage-1 degree counters for the next graph replay
    for (int i = g * 128 + t; i < N0; i += BGR * 128) cnt0z[i] = 0;
}

// ---------------- host side ----------------
extern "C" void kernel_launch(void* const* d_in, const int* in_sizes, int n_in,
                              void* d_out, int out_size) {
    const float* x   = (const float*)d_in[0];
    const int*   src = (const int*)d_in[1];
    const int*   dst = (const int*)d_in[2];
    const float* W1 = (const float*)d_in[3];
    const float* b1 = (const float*)d_in[4];
    const float* A1 = (const float*)d_in[5];
    const float* ps1W = (const float*)d_in[6];
    const float* ps1b = (const float*)d_in[7];
    const float* W2 = (const float*)d_in[8];
    const float* b2 = (const float*)d_in[9];
    const float* A2 = (const float*)d_in[10];
    const float* ps2W = (const float*)d_in[11];
    const float* ps2b = (const float*)d_in[12];
    const float* W3 = (const float*)d_in[13];
    const float* b3 = (const float*)d_in[14];
    const float* A3 = (const float*)d_in[15];
    const float* ps3W = (const float*)d_in[16];
    const float* ps3b = (const float*)d_in[17];
    const float* l1W = (const float*)d_in[18];
    const float* l1b = (const float*)d_in[19];
    const float* l2W = (const float*)d_in[20];
    const float* l2b = (const float*)d_in[21];
    const float* l3W = (const float*)d_in[22];
    const float* l3b = (const float*)d_in[23];
    float* out = (float*)d_out;

    float *X, *XS, *catd, *r;
    int *cnt0, *cnt1, *cnt2, *csrA, *csrB;
    cudaGetSymbolAddress((void**)&X, g_X);
    cudaGetSymbolAddress((void**)&XS, g_XS);
    cudaGetSymbolAddress((void**)&catd, g_catd);
    cudaGetSymbolAddress((void**)&r, g_r);
    cudaGetSymbolAddress((void**)&cnt0, g_cnt0);
    cudaGetSymbolAddress((void**)&cnt1, g_cnt1);
    cudaGetSymbolAddress((void**)&cnt2, g_cnt2);
    cudaGetSymbolAddress((void**)&csrA, g_csrA);
    cudaGetSymbolAddress((void**)&csrB, g_csrB);

    // cnt0 is zero here: zero-init at load, re-zeroed by k_mlp at end of each call
    k_build<<<ceil_div(NE, 256), 256>>>(src, dst, cnt0, csrA);

    // stage 1
    k_scale<<<ceil_div(N0 * 32, 256), 256>>>(x, cnt0, XS, N0);
    k_aggXP<<<ceil_div(N0, NPB3), 256>>>(XS, cnt0, csrA,
                                         W1, b1, A1, ps1W, X, catd, N0);
    k_select<<<BGR, 512>>>(catd, cnt0, csrA, ps1b, X,
                           XS, r, NPER0, KK1, 0, csrB, cnt1);
    // stage 2 (XS already prescaled by select)
    k_aggXP<<<ceil_div(N1, NPB3), 256>>>(XS, cnt1, csrB,
                                         W2, b2, A2, ps2W, X, catd, N1);
    k_select<<<BGR, 512>>>(catd, cnt1, csrB, ps2b, X,
                           XS, r, KK1, KK2, 1, csrA, cnt2);
    // stage 3
    k_aggXP<<<ceil_div(N2, NPB3), 256>>>(XS, cnt2, csrA,
                                         W3, b3, A3, ps3W, X, catd, N2);
    k_select<<<BGR, 512>>>(catd, cnt2, csrA, ps3b, X,
                           nullptr, r, KK2, KK3, 1, nullptr, nullptr);

    k_mlp<<<BGR, 128>>>(r, l1W, l1b, l2W, l2b, l3W, l3b, out, cnt0);
}

// round 11
// speedup vs baseline: 1.4418x; 1.2530x over previous
#include <cuda_runtime.h>
#include <cuda_bf16.h>
#include <math.h>
#include <float.h>

#define BGR   32
#define NPER0 1024
#define N0    (BGR * NPER0)
#define HID   128
#define NE    524288
#define KK1   512
#define KK2   256
#define KK3   128
#define NC    10
#define MAXDEG 128
#define N1    (BGR * KK1)
#define N2    (BGR * KK2)

// ---------------- scratch (static device memory) ----------------
__device__ __align__(16) float g_X[N0 * HID];
__device__ __align__(16) float g_XS[N0 * HID];
__device__ float g_catd[N0];
__device__ int   g_cnt0[N0];     // zero at load; re-zeroed by k_mlp
__device__ int   g_cnt1[N1];
__device__ int   g_cnt2[N2];
__device__ int   g_csrA[N0 * MAXDEG];
__device__ int   g_csrB[N1 * MAXDEG];
__device__ __align__(16) float g_r[BGR * 2 * HID];

static inline int ceil_div(int a, int b) { return (a + b - 1) / b; }

__device__ __forceinline__ unsigned f2u_ord(float f) {
    unsigned u = __float_as_uint(f);
    return (u & 0x80000000u) ? ~u : (u | 0x80000000u);
}
__device__ __forceinline__ float u2f_ord(unsigned m) {
    unsigned u = (m & 0x80000000u) ? (m & 0x7FFFFFFFu) : ~m;
    return __uint_as_float(u);
}

// ---------------- kernels ----------------
__global__ void k_build(const int* __restrict__ src, const int* __restrict__ dst,
                        int* __restrict__ cnt, int* __restrict__ csr) {
    int e = blockIdx.x * blockDim.x + threadIdx.x;
    if (e >= NE) return;
    int d = dst[e];
    int slot = atomicAdd(&cnt[d], 1);
    if (slot < MAXDEG) csr[d * MAXDEG + slot] = src[e];
}

__global__ void k_scale(const float* __restrict__ Xin, const int* __restrict__ cnt,
                        float* __restrict__ Xs, int n) {
    int i = blockIdx.x * blockDim.x + threadIdx.x;
    if (i >= n * 32) return;
    float d = rsqrtf((float)(cnt[i >> 5] + 1));
    float4 v = ((const float4*)Xin)[i];
    ((float4*)Xs)[i] = make_float4(v.x * d, v.y * d, v.z * d, v.w * d);
}

// Warp-per-node fused agg + per-head projection + relu + attention (frozen).
#define NPB3 32
__global__ void __launch_bounds__(256) k_aggXP(
        const float* __restrict__ Xs, const int* __restrict__ cnt,
        const int* __restrict__ csr,
        const float* __restrict__ W, const float* __restrict__ b,
        const float* __restrict__ A, const float* __restrict__ psW,
        float* __restrict__ Xout, float* __restrict__ catd, int n) {
    __shared__ float sW[4096];
    int t = threadIdx.x;
    #pragma unroll
    for (int i = 0; i < 16; i++) sW[i * 256 + t] = W[i * 256 + t];
    __syncthreads();
    int w = t >> 5, lane = t & 31;
    int head = lane >> 3;
    int baseLane = head << 3;
    int oct = lane & 7;
    const float4* Xs4 = (const float4*)Xs;
    float4 b4  = ((const float4*)b)[lane];
    float4 A4  = ((const float4*)A)[lane];
    float4 pw4 = ((const float4*)psW)[lane];
    const float* whBase = sW + head * 1024 + oct * 4;
    int base = blockIdx.x * NPB3;
    #pragma unroll 1
    for (int it = 0; it < NPB3 / 8; it++) {
        int node = base + it * 8 + w;
        if (node >= n) break;
        int deg = cnt[node];
        float di = rsqrtf((float)(deg + 1));
        const int* row = csr + (size_t)node * MAXDEG;
        float4 acc = Xs4[(size_t)node * 32 + lane];
        int j = 0;
        for (; j + 4 <= deg; j += 4) {
            int4 s4 = *(const int4*)(row + j);
            float4 v0 = Xs4[(size_t)s4.x * 32 + lane];
            float4 v1 = Xs4[(size_t)s4.y * 32 + lane];
            float4 v2 = Xs4[(size_t)s4.z * 32 + lane];
            float4 v3 = Xs4[(size_t)s4.w * 32 + lane];
            acc.x += (v0.x + v1.x) + (v2.x + v3.x);
            acc.y += (v0.y + v1.y) + (v2.y + v3.y);
            acc.z += (v0.z + v1.z) + (v2.z + v3.z);
            acc.w += (v0.w + v1.w) + (v2.w + v3.w);
        }
        for (; j < deg; j++) {
            float4 v0 = Xs4[(size_t)row[j] * 32 + lane];
            acc.x += v0.x; acc.y += v0.y; acc.z += v0.z; acc.w += v0.w;
        }
        float4 v = make_float4(acc.x * di, acc.y * di, acc.z * di, acc.w * di);
        float4 o = make_float4(0.f, 0.f, 0.f, 0.f);
        #pragma unroll
        for (int i = 0; i < 8; i++) {
            int sl = baseLane + i;
            float vv0 = __shfl_sync(0xffffffffu, v.x, sl);
            float vv1 = __shfl_sync(0xffffffffu, v.y, sl);
            float vv2 = __shfl_sync(0xffffffffu, v.z, sl);
            float vv3 = __shfl_sync(0xffffffffu, v.w, sl);
            const float* wp = whBase + (i * 4) * 32;
            float4 w0 = *(const float4*)(wp);
            float4 w1 = *(const float4*)(wp + 32);
            float4 w2 = *(const float4*)(wp + 64);
            float4 w3 = *(const float4*)(wp + 96);
            o.x = fmaf(vv0, w0.x, o.x); o.y = fmaf(vv0, w0.y, o.y);
            o.z = fmaf(vv0, w0.z, o.z); o.w = fmaf(vv0, w0.w, o.w);
            o.x = fmaf(vv1, w1.x, o.x); o.y = fmaf(vv1, w1.y, o.y);
            o.z = fmaf(vv1, w1.z, o.z); o.w = fmaf(vv1, w1.w, o.w);
            o.x = fmaf(vv2, w2.x, o.x); o.y = fmaf(vv2, w2.y, o.y);
            o.z = fmaf(vv2, w2.z, o.z); o.w = fmaf(vv2, w2.w, o.w);
            o.x = fmaf(vv3, w3.x, o.x); o.y = fmaf(vv3, w3.y, o.y);
            o.z = fmaf(vv3, w3.z, o.z); o.w = fmaf(vv3, w3.w, o.w);
        }
        o.x = fmaxf(o.x + b4.x, 0.f);
        o.y = fmaxf(o.y + b4.y, 0.f);
        o.z = fmaxf(o.z + b4.z, 0.f);
        o.w = fmaxf(o.w + b4.w, 0.f);
        ((float4*)Xout)[(size_t)node * 32 + lane] = o;
        float att = o.x * A4.x + o.y * A4.y + o.z * A4.z + o.w * A4.w;
        att += __shfl_xor_sync(0xffffffffu, att, 1);
        att += __shfl_xor_sync(0xffffffffu, att, 2);
        att += __shfl_xor_sync(0xffffffffu, att, 4);
        float cp = att * (o.x * pw4.x + o.y * pw4.y + o.z * pw4.z + o.w * pw4.w);
        #pragma unroll
        for (int ofs = 16; ofs > 0; ofs >>= 1)
            cp += __shfl_xor_sync(0xffffffffu, cp, ofs);
        if (lane == 0) catd[node] = cp * di;
    }
}

// Per-graph select, 1024 threads: score gather + bitonic sort (1 cmp/thread/step)
// + CSR->CSR compaction + hoisted tanh + vectorized pool/readout.
__global__ void __launch_bounds__(1024) k_select(
        const float* __restrict__ catd,
        const int* __restrict__ cnt, const int* __restrict__ csrIn,
        const float* __restrict__ psb, const float* __restrict__ Xmid,
        float* __restrict__ XSout, float* __restrict__ r,
        int nper, int k, int accum,
        int* __restrict__ csrOut, int* __restrict__ cntOut) {
    __shared__ unsigned long long skey[1024];   // 8K
    __shared__ float scd[1024];                 // 4K (scores, then tanh)
    __shared__ int   snmap[1024];               // 4K
    __shared__ int   sdeg[512];                 // 2K
    __shared__ float4 sred[1024];               // 16K (reused: max then sum)
    int g = blockIdx.x, t = threadIdx.x;        // 1024 threads
    int base = g * nper;
    if (t < nper) {
        scd[t] = catd[base + t];
        snmap[t] = -1;
    }
    __syncthreads();
    float pb = psb[0];
    if (t < nper) {
        int node = base + t;
        int deg = cnt[node];
        const int* row = csrIn + (size_t)node * MAXDEG;
        float din = rsqrtf((float)(deg + 1));
        float s2 = scd[t] * din;
        for (int j = 0; j < deg; j++) s2 += scd[row[j] - base];
        float sc = fmaf(s2, din, pb);
        skey[t] = ((unsigned long long)f2u_ord(sc) << 32) | (unsigned)(~t);
    }
    __syncthreads();
    for (int ks = 2; ks <= nper; ks <<= 1) {
        for (int j = ks >> 1; j > 0; j >>= 1) {
            int i = t;
            if (i < nper) {
                int ixj = i ^ j;
                if (ixj > i) {
                    unsigned long long ka = skey[i], kb = skey[ixj];
                    bool dirUp = ((i & ks) == 0);
                    bool sw = dirUp ? (ka < kb) : (ka > kb);
                    if (sw) { skey[i] = kb; skey[ixj] = ka; }
                }
            }
            __syncthreads();
        }
    }
    // nmap + hoisted tanh (scd reused as tanh(score) of rank j)
    if (t < k) {
        unsigned long long key = skey[t];
        snmap[(int)(~(unsigned)key)] = g * k + t;
        scd[t] = tanhf(u2f_ord((unsigned)(key >> 32)));
    }
    __syncthreads();
    // CSR -> CSR compaction (thread-per-row, zero atomics); fills sdeg
    if (csrOut) {
        if (t < nper) {
            int nm = snmap[t];
            if (nm >= 0) {
                int node = base + t;
                int deg = cnt[node];
                const int* row = csrIn + (size_t)node * MAXDEG;
                int* orow = csrOut + (size_t)nm * MAXDEG;
                int cct = 0;
                for (int j = 0; j < deg; j++) {
                    int m2 = snmap[row[j] - base];
                    if (m2 >= 0) orow[cct++] = m2;
                }
                cntOut[nm] = cct;
                sdeg[nm - g * k] = cct;
            }
        }
        __syncthreads();
    }
    // vectorized pool + readout: c = warp (rank group), f4 = lane (float4 of features)
    int f4 = t & 31, c = t >> 5;
    const float4* Xmid4 = (const float4*)Xmid;
    float4 mx = make_float4(-FLT_MAX, -FLT_MAX, -FLT_MAX, -FLT_MAX);
    float4 sm = make_float4(0.f, 0.f, 0.f, 0.f);
    for (int j = c; j < k; j += 32) {
        int orig = base + (int)(~(unsigned)skey[j]);
        float tv = scd[j];
        float4 v = Xmid4[(size_t)orig * 32 + f4];
        v.x *= tv; v.y *= tv; v.z *= tv; v.w *= tv;
        if (XSout) {
            float dn = rsqrtf((float)(sdeg[j] + 1));
            ((float4*)XSout)[(size_t)(g * k + j) * 32 + f4] =
                make_float4(v.x * dn, v.y * dn, v.z * dn, v.w * dn);
        }
        mx.x = fmaxf(mx.x, v.x); mx.y = fmaxf(mx.y, v.y);
        mx.z = fmaxf(mx.z, v.z); mx.w = fmaxf(mx.w, v.w);
        sm.x += v.x; sm.y += v.y; sm.z += v.z; sm.w += v.w;
    }
    // reduce max across 32 rank-groups
    sred[c * 32 + f4] = mx;
    __syncthreads();
    for (int st = 16; st >= 1; st >>= 1) {
        if (c < st) {
            float4 a = sred[c * 32 + f4], bb = sred[(c + st) * 32 + f4];
            sred[c * 32 + f4] = make_float4(fmaxf(a.x, bb.x), fmaxf(a.y, bb.y),
                                            fmaxf(a.z, bb.z), fmaxf(a.w, bb.w));
        }
        __syncthreads();
    }
    if (t < 32) {
        float4 o = sred[f4];
        float4* rp = (float4*)(r + g * 256) + f4;
        if (accum) {
            float4 old = *rp;
            o.x += old.x; o.y += old.y; o.z += old.z; o.w += old.w;
        }
        *rp = o;
    }
    __syncthreads();
    // reduce sum across 32 rank-groups (reuse sred)
    sred[c * 32 + f4] = sm;
    __syncthreads();
    for (int st = 16; st >= 1; st >>= 1) {
        if (c < st) {
            float4 a = sred[c * 32 + f4], bb = sred[(c + st) * 32 + f4];
            sred[c * 32 + f4] = make_float4(a.x + bb.x, a.y + bb.y,
                                            a.z + bb.z, a.w + bb.w);
        }
        __syncthreads();
    }
    if (t < 32) {
        float4 o = sred[f4];
        float inv = 1.0f / (float)k;
        o.x *= inv; o.y *= inv; o.z *= inv; o.w *= inv;
        float4* rp = (float4*)(r + g * 256 + 128) + f4;
        if (accum) {
            float4 old = *rp;
            o.x += old.x; o.y += old.y; o.z += old.z; o.w += old.w;
        }
        *rp = o;
    }
}

__global__ void k_mlp(const float* __restrict__ r,
                      const float* __restrict__ l1W, const float* __restrict__ l1b,
                      const float* __restrict__ l2W, const float* __restrict__ l2b,
                      const float* __restrict__ l3W, const float* __restrict__ l3b,
                      float* __restrict__ out, int* __restrict__ cnt0z) {
    __shared__ float z0[256], z1[128], z2[64], z3[16];
    __shared__ float red2[2];
    int g = blockIdx.x, t = threadIdx.x;
    z0[t] = r[g * 256 + t];
    z0[t + 128] = r[g * 256 + 128 + t];
    __syncthreads();
    {
        float acc = l1b[t];
        for (int i = 0; i < 256; i++) acc = fmaf(z0[i], l1W[i * 128 + t], acc);
        z1[t] = fmaxf(acc, 0.f);
    }
    __syncthreads();
    if (t < 64) {
        float acc = l2b[t];
        for (int i = 0; i < 128; i++) acc = fmaf(z1[i], l2W[i * 64 + t], acc);
        z2[t] = fmaxf(acc, 0.f);
    }
    __syncthreads();
    if (t < NC) {
        float acc = l3b[t];
        for (int i = 0; i < 64; i++) acc = fmaf(z2[i], l3W[i * NC + t], acc);
        z3[t] = acc;
    }
    __syncthreads();
    if (t == 0) {
        float m = -FLT_MAX;
        for (int c = 0; c < NC; c++) m = fmaxf(m, z3[c]);
        float s = 0.f;
        for (int c = 0; c < NC; c++) s += expf(z3[c] - m);
        red2[0] = m; red2[1] = logf(s);
    }
    __syncthreads();
    if (t < NC) out[g * NC + t] = z3[t] - red2[0] - red2[1];
    for (int i = g * 128 + t; i < N0; i += BGR * 128) cnt0z[i] = 0;
}

// ---------------- host side ----------------
extern "C" void kernel_launch(void* const* d_in, const int* in_sizes, int n_in,
                              void* d_out, int out_size) {
    const float* x   = (const float*)d_in[0];
    const int*   src = (const int*)d_in[1];
    const int*   dst = (const int*)d_in[2];
    const float* W1 = (const float*)d_in[3];
    const float* b1 = (const float*)d_in[4];
    const float* A1 = (const float*)d_in[5];
    const float* ps1W = (const float*)d_in[6];
    const float* ps1b = (const float*)d_in[7];
    const float* W2 = (const float*)d_in[8];
    const float* b2 = (const float*)d_in[9];
    const float* A2 = (const float*)d_in[10];
    const float* ps2W = (const float*)d_in[11];
    const float* ps2b = (const float*)d_in[12];
    const float* W3 = (const float*)d_in[13];
    const float* b3 = (const float*)d_in[14];
    const float* A3 = (const float*)d_in[15];
    const float* ps3W = (const float*)d_in[16];
    const float* ps3b = (const float*)d_in[17];
    const float* l1W = (const float*)d_in[18];
    const float* l1b = (const float*)d_in[19];
    const float* l2W = (const float*)d_in[20];
    const float* l2b = (const float*)d_in[21];
    const float* l3W = (const float*)d_in[22];
    const float* l3b = (const float*)d_in[23];
    float* out = (float*)d_out;

    float *X, *XS, *catd, *r;
    int *cnt0, *cnt1, *cnt2, *csrA, *csrB;
    cudaGetSymbolAddress((void**)&X, g_X);
    cudaGetSymbolAddress((void**)&XS, g_XS);
    cudaGetSymbolAddress((void**)&catd, g_catd);
    cudaGetSymbolAddress((void**)&r, g_r);
    cudaGetSymbolAddress((void**)&cnt0, g_cnt0);
    cudaGetSymbolAddress((void**)&cnt1, g_cnt1);
    cudaGetSymbolAddress((void**)&cnt2, g_cnt2);
    cudaGetSymbolAddress((void**)&csrA, g_csrA);
    cudaGetSymbolAddress((void**)&csrB, g_csrB);

    k_build<<<ceil_div(NE, 256), 256>>>(src, dst, cnt0, csrA);

    // stage 1
    k_scale<<<ceil_div(N0 * 32, 256), 256>>>(x, cnt0, XS, N0);
    k_aggXP<<<ceil_div(N0, NPB3), 256>>>(XS, cnt0, csrA,
                                         W1, b1, A1, ps1W, X, catd, N0);
    k_select<<<BGR, 1024>>>(catd, cnt0, csrA, ps1b, X,
                            XS, r, NPER0, KK1, 0, csrB, cnt1);
    // stage 2
    k_aggXP<<<ceil_div(N1, NPB3), 256>>>(XS, cnt1, csrB,
                                         W2, b2, A2, ps2W, X, catd, N1);
    k_select<<<BGR, 1024>>>(catd, cnt1, csrB, ps2b, X,
                            XS, r, KK1, KK2, 1, csrA, cnt2);
    // stage 3
    k_aggXP<<<ceil_div(N2, NPB3), 256>>>(XS, cnt2, csrA,
                                         W3, b3, A3, ps3W, X, catd, N2);
    k_select<<<BGR, 1024>>>(catd, cnt2, csrA, ps3b, X,
                            nullptr, r, KK2, KK3, 1, nullptr, nullptr);

    k_mlp<<<BGR, 128>>>(r, l1W, l1b, l2W, l2b, l3W, l3b, out, cnt0);
}

// round 12
// speedup vs baseline: 1.5068x; 1.0451x over previous
#include <cuda_runtime.h>
#include <cuda_fp16.h>
#include <math.h>
#include <float.h>

#define BGR   32
#define NPER0 1024
#define N0    (BGR * NPER0)
#define HID   128
#define NE    524288
#define KK1   512
#define KK2   256
#define KK3   128
#define NC    10
#define MAXDEG 128
#define N1    (BGR * KK1)
#define N2    (BGR * KK2)

// ---------------- scratch (static device memory) ----------------
__device__ __align__(16) float  g_X[N0 * HID];    // post-layer output (fp32)
__device__ __align__(16) __half g_XS[N0 * HID];   // prescaled stage input (fp16)
__device__ float g_catd[N0];
__device__ int   g_cnt0[N0];     // zero at load; re-zeroed by k_mlp
__device__ int   g_cnt1[N1];
__device__ int   g_cnt2[N2];
__device__ int   g_csrA[N0 * MAXDEG];
__device__ int   g_csrB[N1 * MAXDEG];
__device__ __align__(16) float g_r[BGR * 2 * HID];

static inline int ceil_div(int a, int b) { return (a + b - 1) / b; }

__device__ __forceinline__ unsigned f2u_ord(float f) {
    unsigned u = __float_as_uint(f);
    return (u & 0x80000000u) ? ~u : (u | 0x80000000u);
}
__device__ __forceinline__ float u2f_ord(unsigned m) {
    unsigned u = (m & 0x80000000u) ? (m & 0x7FFFFFFFu) : ~m;
    return __uint_as_float(u);
}

// pack 4 floats -> uint2 of 2x half2 ; unpack back to float4
__device__ __forceinline__ uint2 pack_h4(float a, float b, float c, float d) {
    union { uint2 u; __half2 h[2]; } pk;
    pk.h[0] = __floats2half2_rn(a, b);
    pk.h[1] = __floats2half2_rn(c, d);
    return pk.u;
}
__device__ __forceinline__ float4 unpack_h4(uint2 u) {
    union { uint2 u; __half2 h[2]; } pk;
    pk.u = u;
    float2 f0 = __half22float2(pk.h[0]);
    float2 f1 = __half22float2(pk.h[1]);
    return make_float4(f0.x, f0.y, f1.x, f1.y);
}

// ---------------- kernels ----------------
__global__ void k_build(const int* __restrict__ src, const int* __restrict__ dst,
                        int* __restrict__ cnt, int* __restrict__ csr) {
    int e = blockIdx.x * blockDim.x + threadIdx.x;
    if (e >= NE) return;
    int d = dst[e];
    int slot = atomicAdd(&cnt[d], 1);
    if (slot < MAXDEG) csr[d * MAXDEG + slot] = src[e];
}

// stage-1 prescale: XS(fp16) = x * rsqrt(deg)
__global__ void k_scale(const float* __restrict__ Xin, const int* __restrict__ cnt,
                        __half* __restrict__ Xs, int n) {
    int i = blockIdx.x * blockDim.x + threadIdx.x;
    if (i >= n * 32) return;
    float d = rsqrtf((float)(cnt[i >> 5] + 1));
    float4 v = ((const float4*)Xin)[i];
    ((uint2*)Xs)[i] = pack_h4(v.x * d, v.y * d, v.z * d, v.w * d);
}

// Warp-per-node fused agg(fp16 gather) + per-head projection + relu + attention.
#define NPB3 32
__global__ void __launch_bounds__(256) k_aggXP(
        const __half* __restrict__ Xs, const int* __restrict__ cnt,
        const int* __restrict__ csr,
        const float* __restrict__ W, const float* __restrict__ b,
        const float* __restrict__ A, const float* __restrict__ psW,
        float* __restrict__ Xout, float* __restrict__ catd, int n) {
    __shared__ float sW[4096];
    int t = threadIdx.x;
    #pragma unroll
    for (int i = 0; i < 16; i++) sW[i * 256 + t] = W[i * 256 + t];
    __syncthreads();
    int w = t >> 5, lane = t & 31;
    int head = lane >> 3;
    int baseLane = head << 3;
    int oct = lane & 7;
    const uint2* Xh = (const uint2*)Xs;
    float4 b4  = ((const float4*)b)[lane];
    float4 A4  = ((const float4*)A)[lane];
    float4 pw4 = ((const float4*)psW)[lane];
    const float* whBase = sW + head * 1024 + oct * 4;
    int base = blockIdx.x * NPB3;
    #pragma unroll 1
    for (int it = 0; it < NPB3 / 8; it++) {
        int node = base + it * 8 + w;
        if (node >= n) break;
        int deg = cnt[node];
        float di = rsqrtf((float)(deg + 1));
        const int* row = csr + (size_t)node * MAXDEG;
        float4 acc = unpack_h4(Xh[(size_t)node * 32 + lane]);   // self term
        int j = 0;
        for (; j + 4 <= deg; j += 4) {
            int4 s4 = *(const int4*)(row + j);
            float4 v0 = unpack_h4(Xh[(size_t)s4.x * 32 + lane]);
            float4 v1 = unpack_h4(Xh[(size_t)s4.y * 32 + lane]);
            float4 v2 = unpack_h4(Xh[(size_t)s4.z * 32 + lane]);
            float4 v3 = unpack_h4(Xh[(size_t)s4.w * 32 + lane]);
            acc.x += (v0.x + v1.x) + (v2.x + v3.x);
            acc.y += (v0.y + v1.y) + (v2.y + v3.y);
            acc.z += (v0.z + v1.z) + (v2.z + v3.z);
            acc.w += (v0.w + v1.w) + (v2.w + v3.w);
        }
        for (; j < deg; j++) {
            float4 v0 = unpack_h4(Xh[(size_t)row[j] * 32 + lane]);
            acc.x += v0.x; acc.y += v0.y; acc.z += v0.z; acc.w += v0.w;
        }
        float4 v = make_float4(acc.x * di, acc.y * di, acc.z * di, acc.w * di);
        float4 o = make_float4(0.f, 0.f, 0.f, 0.f);
        #pragma unroll
        for (int i = 0; i < 8; i++) {
            int sl = baseLane + i;
            float vv0 = __shfl_sync(0xffffffffu, v.x, sl);
            float vv1 = __shfl_sync(0xffffffffu, v.y, sl);
            float vv2 = __shfl_sync(0xffffffffu, v.z, sl);
            float vv3 = __shfl_sync(0xffffffffu, v.w, sl);
            const float* wp = whBase + (i * 4) * 32;
            float4 w0 = *(const float4*)(wp);
            float4 w1 = *(const float4*)(wp + 32);
            float4 w2 = *(const float4*)(wp + 64);
            float4 w3 = *(const float4*)(wp + 96);
            o.x = fmaf(vv0, w0.x, o.x); o.y = fmaf(vv0, w0.y, o.y);
            o.z = fmaf(vv0, w0.z, o.z); o.w = fmaf(vv0, w0.w, o.w);
            o.x = fmaf(vv1, w1.x, o.x); o.y = fmaf(vv1, w1.y, o.y);
            o.z = fmaf(vv1, w1.z, o.z); o.w = fmaf(vv1, w1.w, o.w);
            o.x = fmaf(vv2, w2.x, o.x); o.y = fmaf(vv2, w2.y, o.y);
            o.z = fmaf(vv2, w2.z, o.z); o.w = fmaf(vv2, w2.w, o.w);
            o.x = fmaf(vv3, w3.x, o.x); o.y = fmaf(vv3, w3.y, o.y);
            o.z = fmaf(vv3, w3.z, o.z); o.w = fmaf(vv3, w3.w, o.w);
        }
        o.x = fmaxf(o.x + b4.x, 0.f);
        o.y = fmaxf(o.y + b4.y, 0.f);
        o.z = fmaxf(o.z + b4.z, 0.f);
        o.w = fmaxf(o.w + b4.w, 0.f);
        ((float4*)Xout)[(size_t)node * 32 + lane] = o;
        float att = o.x * A4.x + o.y * A4.y + o.z * A4.z + o.w * A4.w;
        att += __shfl_xor_sync(0xffffffffu, att, 1);
        att += __shfl_xor_sync(0xffffffffu, att, 2);
        att += __shfl_xor_sync(0xffffffffu, att, 4);
        float cp = att * (o.x * pw4.x + o.y * pw4.y + o.z * pw4.z + o.w * pw4.w);
        #pragma unroll
        for (int ofs = 16; ofs > 0; ofs >>= 1)
            cp += __shfl_xor_sync(0xffffffffu, cp, ofs);
        if (lane == 0) catd[node] = cp * di;
    }
}

// Per-graph select, 1024 threads (R11 structure; pool writes fp16 XS).
__global__ void __launch_bounds__(1024) k_select(
        const float* __restrict__ catd,
        const int* __restrict__ cnt, const int* __restrict__ csrIn,
        const float* __restrict__ psb, const float* __restrict__ Xmid,
        __half* __restrict__ XSout, float* __restrict__ r,
        int nper, int k, int accum,
        int* __restrict__ csrOut, int* __restrict__ cntOut) {
    __shared__ unsigned long long skey[1024];
    __shared__ float scd[1024];
    __shared__ int   snmap[1024];
    __shared__ int   sdeg[512];
    __shared__ float4 sred[1024];
    int g = blockIdx.x, t = threadIdx.x;
    int base = g * nper;
    if (t < nper) {
        scd[t] = catd[base + t];
        snmap[t] = -1;
    }
    __syncthreads();
    float pb = psb[0];
    if (t < nper) {
        int node = base + t;
        int deg = cnt[node];
        const int* row = csrIn + (size_t)node * MAXDEG;
        float din = rsqrtf((float)(deg + 1));
        float s2 = scd[t] * din;
        for (int j = 0; j < deg; j++) s2 += scd[row[j] - base];
        float sc = fmaf(s2, din, pb);
        skey[t] = ((unsigned long long)f2u_ord(sc) << 32) | (unsigned)(~t);
    }
    __syncthreads();
    for (int ks = 2; ks <= nper; ks <<= 1) {
        for (int j = ks >> 1; j > 0; j >>= 1) {
            int i = t;
            if (i < nper) {
                int ixj = i ^ j;
                if (ixj > i) {
                    unsigned long long ka = skey[i], kb = skey[ixj];
                    bool dirUp = ((i & ks) == 0);
                    bool sw = dirUp ? (ka < kb) : (ka > kb);
                    if (sw) { skey[i] = kb; skey[ixj] = ka; }
                }
            }
            __syncthreads();
        }
    }
    if (t < k) {
        unsigned long long key = skey[t];
        snmap[(int)(~(unsigned)key)] = g * k + t;
        scd[t] = tanhf(u2f_ord((unsigned)(key >> 32)));
    }
    __syncthreads();
    if (csrOut) {
        if (t < nper) {
            int nm = snmap[t];
            if (nm >= 0) {
                int node = base + t;
                int deg = cnt[node];
                const int* row = csrIn + (size_t)node * MAXDEG;
                int* orow = csrOut + (size_t)nm * MAXDEG;
                int cct = 0;
                for (int j = 0; j < deg; j++) {
                    int m2 = snmap[row[j] - base];
                    if (m2 >= 0) orow[cct++] = m2;
                }
                cntOut[nm] = cct;
                sdeg[nm - g * k] = cct;
            }
        }
        __syncthreads();
    }
    int f4 = t & 31, c = t >> 5;
    const float4* Xmid4 = (const float4*)Xmid;
    float4 mx = make_float4(-FLT_MAX, -FLT_MAX, -FLT_MAX, -FLT_MAX);
    float4 sm = make_float4(0.f, 0.f, 0.f, 0.f);
    for (int j = c; j < k; j += 32) {
        int orig = base + (int)(~(unsigned)skey[j]);
        float tv = scd[j];
        float4 v = Xmid4[(size_t)orig * 32 + f4];
        v.x *= tv; v.y *= tv; v.z *= tv; v.w *= tv;
        if (XSout) {
            float dn = rsqrtf((float)(sdeg[j] + 1));
            ((uint2*)XSout)[(size_t)(g * k + j) * 32 + f4] =
                pack_h4(v.x * dn, v.y * dn, v.z * dn, v.w * dn);
        }
        mx.x = fmaxf(mx.x, v.x); mx.y = fmaxf(mx.y, v.y);
        mx.z = fmaxf(mx.z, v.z); mx.w = fmaxf(mx.w, v.w);
        sm.x += v.x; sm.y += v.y; sm.z += v.z; sm.w += v.w;
    }
    sred[c * 32 + f4] = mx;
    __syncthreads();
    for (int st = 16; st >= 1; st >>= 1) {
        if (c < st) {
            float4 a = sred[c * 32 + f4], bb = sred[(c + st) * 32 + f4];
            sred[c * 32 + f4] = make_float4(fmaxf(a.x, bb.x), fmaxf(a.y, bb.y),
                                            fmaxf(a.z, bb.z), fmaxf(a.w, bb.w));
        }
        __syncthreads();
    }
    if (t < 32) {
        float4 o = sred[f4];
        float4* rp = (float4*)(r + g * 256) + f4;
        if (accum) {
            float4 old = *rp;
            o.x += old.x; o.y += old.y; o.z += old.z; o.w += old.w;
        }
        *rp = o;
    }
    __syncthreads();
    sred[c * 32 + f4] = sm;
    __syncthreads();
    for (int st = 16; st >= 1; st >>= 1) {
        if (c < st) {
            float4 a = sred[c * 32 + f4], bb = sred[(c + st) * 32 + f4];
            sred[c * 32 + f4] = make_float4(a.x + bb.x, a.y + bb.y,
                                            a.z + bb.z, a.w + bb.w);
        }
        __syncthreads();
    }
    if (t < 32) {
        float4 o = sred[f4];
        float inv = 1.0f / (float)k;
        o.x *= inv; o.y *= inv; o.z *= inv; o.w *= inv;
        float4* rp = (float4*)(r + g * 256 + 128) + f4;
        if (accum) {
            float4 old = *rp;
            o.x += old.x; o.y += old.y; o.z += old.z; o.w += old.w;
        }
        *rp = o;
    }
}

__global__ void k_mlp(const float* __restrict__ r,
                      const float* __restrict__ l1W, const float* __restrict__ l1b,
                      const float* __restrict__ l2W, const float* __restrict__ l2b,
                      const float* __restrict__ l3W, const float* __restrict__ l3b,
                      float* __restrict__ out, int* __restrict__ cnt0z) {
    __shared__ float z0[256], z1[128], z2[64], z3[16];
    __shared__ float red2[2];
    int g = blockIdx.x, t = threadIdx.x;
    z0[t] = r[g * 256 + t];
    z0[t + 128] = r[g * 256 + 128 + t];
    __syncthreads();
    {
        float acc = l1b[t];
        for (int i = 0; i < 256; i++) acc = fmaf(z0[i], l1W[i * 128 + t], acc);
        z1[t] = fmaxf(acc, 0.f);
    }
    __syncthreads();
    if (t < 64) {
        float acc = l2b[t];
        for (int i = 0; i < 128; i++) acc = fmaf(z1[i], l2W[i * 64 + t], acc);
        z2[t] = fmaxf(acc, 0.f);
    }
    __syncthreads();
    if (t < NC) {
        float acc = l3b[t];
        for (int i = 0; i < 64; i++) acc = fmaf(z2[i], l3W[i * NC + t], acc);
        z3[t] = acc;
    }
    __syncthreads();
    if (t == 0) {
        float m = -FLT_MAX;
        for (int c = 0; c < NC; c++) m = fmaxf(m, z3[c]);
        float s = 0.f;
        for (int c = 0; c < NC; c++) s += expf(z3[c] - m);
        red2[0] = m; red2[1] = logf(s);
    }
    __syncthreads();
    if (t < NC) out[g * NC + t] = z3[t] - red2[0] - red2[1];
    for (int i = g * 128 + t; i < N0; i += BGR * 128) cnt0z[i] = 0;
}

// ---------------- host side ----------------
extern "C" void kernel_launch(void* const* d_in, const int* in_sizes, int n_in,
                              void* d_out, int out_size) {
    const float* x   = (const float*)d_in[0];
    const int*   src = (const int*)d_in[1];
    const int*   dst = (const int*)d_in[2];
    const float* W1 = (const float*)d_in[3];
    const float* b1 = (const float*)d_in[4];
    const float* A1 = (const float*)d_in[5];
    const float* ps1W = (const float*)d_in[6];
    const float* ps1b = (const float*)d_in[7];
    const float* W2 = (const float*)d_in[8];
    const float* b2 = (const float*)d_in[9];
    const float* A2 = (const float*)d_in[10];
    const float* ps2W = (const float*)d_in[11];
    const float* ps2b = (const float*)d_in[12];
    const float* W3 = (const float*)d_in[13];
    const float* b3 = (const float*)d_in[14];
    const float* A3 = (const float*)d_in[15];
    const float* ps3W = (const float*)d_in[16];
    const float* ps3b = (const float*)d_in[17];
    const float* l1W = (const float*)d_in[18];
    const float* l1b = (const float*)d_in[19];
    const float* l2W = (const float*)d_in[20];
    const float* l2b = (const float*)d_in[21];
    const float* l3W = (const float*)d_in[22];
    const float* l3b = (const float*)d_in[23];
    float* out = (float*)d_out;

    float *X, *catd, *r;
    __half *XS;
    int *cnt0, *cnt1, *cnt2, *csrA, *csrB;
    cudaGetSymbolAddress((void**)&X, g_X);
    cudaGetSymbolAddress((void**)&XS, g_XS);
    cudaGetSymbolAddress((void**)&catd, g_catd);
    cudaGetSymbolAddress((void**)&r, g_r);
    cudaGetSymbolAddress((void**)&cnt0, g_cnt0);
    cudaGetSymbolAddress((void**)&cnt1, g_cnt1);
    cudaGetSymbolAddress((void**)&cnt2, g_cnt2);
    cudaGetSymbolAddress((void**)&csrA, g_csrA);
    cudaGetSymbolAddress((void**)&csrB, g_csrB);

    k_build<<<ceil_div(NE, 256), 256>>>(src, dst, cnt0, csrA);

    // stage 1
    k_scale<<<ceil_div(N0 * 32, 256), 256>>>(x, cnt0, XS, N0);
    k_aggXP<<<ceil_div(N0, NPB3), 256>>>(XS, cnt0, csrA,
                                         W1, b1, A1, ps1W, X, catd, N0);
    k_select<<<BGR, 1024>>>(catd, cnt0, csrA, ps1b, X,
                            XS, r, NPER0, KK1, 0, csrB, cnt1);
    // stage 2
    k_aggXP<<<ceil_div(N1, NPB3), 256>>>(XS, cnt1, csrB,
                                         W2, b2, A2, ps2W, X, catd, N1);
    k_select<<<BGR, 1024>>>(catd, cnt1, csrB, ps2b, X,
                            XS, r, KK1, KK2, 1, csrA, cnt2);
    // stage 3
    k_aggXP<<<ceil_div(N2, NPB3), 256>>>(XS, cnt2, csrA,
                                         W3, b3, A3, ps3W, X, catd, N2);
    k_select<<<BGR, 1024>>>(catd, cnt2, csrA, ps3b, X,
                            nullptr, r, KK2, KK3, 1, nullptr, nullptr);

    k_mlp<<<BGR, 128>>>(r, l1W, l1b, l2W, l2b, l3W, l3b, out, cnt0);
}

// round 13
// speedup vs baseline: 1.5236x; 1.0111x over previous
#include <cuda_runtime.h>
#include <cuda_fp16.h>
#include <math.h>
#include <float.h>

#define BGR   32
#define NPER0 1024
#define N0    (BGR * NPER0)
#define HID   128
#define NE    524288
#define KK1   512
#define KK2   256
#define KK3   128
#define NC    10
#define MAXDEG 128
#define N1    (BGR * KK1)
#define N2    (BGR * KK2)

// ---------------- scratch (static device memory) ----------------
__device__ __align__(16) float  g_X[N0 * HID];
__device__ __align__(16) __half g_XS[N0 * HID];
__device__ float g_catd[N0];
__device__ int   g_cnt0[N0];     // zero at load; re-zeroed by k_mlp
__device__ int   g_cnt1[N1];
__device__ int   g_cnt2[N2];
__device__ int   g_csrA[N0 * MAXDEG];
__device__ int   g_csrB[N1 * MAXDEG];
__device__ __align__(16) float g_r[BGR * 2 * HID];

static inline int ceil_div(int a, int b) { return (a + b - 1) / b; }

__device__ __forceinline__ unsigned f2u_ord(float f) {
    unsigned u = __float_as_uint(f);
    return (u & 0x80000000u) ? ~u : (u | 0x80000000u);
}
__device__ __forceinline__ float u2f_ord(unsigned m) {
    unsigned u = (m & 0x80000000u) ? (m & 0x7FFFFFFFu) : ~m;
    return __uint_as_float(u);
}

__device__ __forceinline__ uint2 pack_h4(float a, float b, float c, float d) {
    union { uint2 u; __half2 h[2]; } pk;
    pk.h[0] = __floats2half2_rn(a, b);
    pk.h[1] = __floats2half2_rn(c, d);
    return pk.u;
}
__device__ __forceinline__ float4 unpack_h4(uint2 u) {
    union { uint2 u; __half2 h[2]; } pk;
    pk.u = u;
    float2 f0 = __half22float2(pk.h[0]);
    float2 f1 = __half22float2(pk.h[1]);
    return make_float4(f0.x, f0.y, f1.x, f1.y);
}

__device__ __forceinline__ unsigned long long shfl_xor_u64(unsigned long long v, int m) {
    unsigned lo = (unsigned)v, hi = (unsigned)(v >> 32);
    lo = __shfl_xor_sync(0xffffffffu, lo, m);
    hi = __shfl_xor_sync(0xffffffffu, hi, m);
    return ((unsigned long long)hi << 32) | lo;
}

// ---------------- kernels ----------------
// stage-1 CSR build, 4 edges per thread for MLP
__global__ void k_build(const int* __restrict__ src, const int* __restrict__ dst,
                        int* __restrict__ cnt, int* __restrict__ csr) {
    int e4 = blockIdx.x * blockDim.x + threadIdx.x;
    if (e4 >= NE / 4) return;
    int4 d4 = ((const int4*)dst)[e4];
    int4 s4 = ((const int4*)src)[e4];
    int t0 = atomicAdd(&cnt[d4.x], 1);
    int t1 = atomicAdd(&cnt[d4.y], 1);
    int t2 = atomicAdd(&cnt[d4.z], 1);
    int t3 = atomicAdd(&cnt[d4.w], 1);
    if (t0 < MAXDEG) csr[d4.x * MAXDEG + t0] = s4.x;
    if (t1 < MAXDEG) csr[d4.y * MAXDEG + t1] = s4.y;
    if (t2 < MAXDEG) csr[d4.z * MAXDEG + t2] = s4.z;
    if (t3 < MAXDEG) csr[d4.w * MAXDEG + t3] = s4.w;
}

__global__ void k_scale(const float* __restrict__ Xin, const int* __restrict__ cnt,
                        __half* __restrict__ Xs, int n) {
    int i = blockIdx.x * blockDim.x + threadIdx.x;
    if (i >= n * 32) return;
    float d = rsqrtf((float)(cnt[i >> 5] + 1));
    float4 v = ((const float4*)Xin)[i];
    ((uint2*)Xs)[i] = pack_h4(v.x * d, v.y * d, v.z * d, v.w * d);
}

// Warp-per-node fused agg(fp16) + per-head projection + relu + attention (frozen).
#define NPB3 32
__global__ void __launch_bounds__(256) k_aggXP(
        const __half* __restrict__ Xs, const int* __restrict__ cnt,
        const int* __restrict__ csr,
        const float* __restrict__ W, const float* __restrict__ b,
        const float* __restrict__ A, const float* __restrict__ psW,
        float* __restrict__ Xout, float* __restrict__ catd, int n) {
    __shared__ float sW[4096];
    int t = threadIdx.x;
    #pragma unroll
    for (int i = 0; i < 16; i++) sW[i * 256 + t] = W[i * 256 + t];
    __syncthreads();
    int w = t >> 5, lane = t & 31;
    int head = lane >> 3;
    int baseLane = head << 3;
    int oct = lane & 7;
    const uint2* Xh = (const uint2*)Xs;
    float4 b4  = ((const float4*)b)[lane];
    float4 A4  = ((const float4*)A)[lane];
    float4 pw4 = ((const float4*)psW)[lane];
    const float* whBase = sW + head * 1024 + oct * 4;
    int base = blockIdx.x * NPB3;
    #pragma unroll 1
    for (int it = 0; it < NPB3 / 8; it++) {
        int node = base + it * 8 + w;
        if (node >= n) break;
        int deg = cnt[node];
        float di = rsqrtf((float)(deg + 1));
        const int* row = csr + (size_t)node * MAXDEG;
        float4 acc = unpack_h4(Xh[(size_t)node * 32 + lane]);
        int j = 0;
        for (; j + 4 <= deg; j += 4) {
            int4 s4 = *(const int4*)(row + j);
            float4 v0 = unpack_h4(Xh[(size_t)s4.x * 32 + lane]);
            float4 v1 = unpack_h4(Xh[(size_t)s4.y * 32 + lane]);
            float4 v2 = unpack_h4(Xh[(size_t)s4.z * 32 + lane]);
            float4 v3 = unpack_h4(Xh[(size_t)s4.w * 32 + lane]);
            acc.x += (v0.x + v1.x) + (v2.x + v3.x);
            acc.y += (v0.y + v1.y) + (v2.y + v3.y);
            acc.z += (v0.z + v1.z) + (v2.z + v3.z);
            acc.w += (v0.w + v1.w) + (v2.w + v3.w);
        }
        for (; j < deg; j++) {
            float4 v0 = unpack_h4(Xh[(size_t)row[j] * 32 + lane]);
            acc.x += v0.x; acc.y += v0.y; acc.z += v0.z; acc.w += v0.w;
        }
        float4 v = make_float4(acc.x * di, acc.y * di, acc.z * di, acc.w * di);
        float4 o = make_float4(0.f, 0.f, 0.f, 0.f);
        #pragma unroll
        for (int i = 0; i < 8; i++) {
            int sl = baseLane + i;
            float vv0 = __shfl_sync(0xffffffffu, v.x, sl);
            float vv1 = __shfl_sync(0xffffffffu, v.y, sl);
            float vv2 = __shfl_sync(0xffffffffu, v.z, sl);
            float vv3 = __shfl_sync(0xffffffffu, v.w, sl);
            const float* wp = whBase + (i * 4) * 32;
            float4 w0 = *(const float4*)(wp);
            float4 w1 = *(const float4*)(wp + 32);
            float4 w2 = *(const float4*)(wp + 64);
            float4 w3 = *(const float4*)(wp + 96);
            o.x = fmaf(vv0, w0.x, o.x); o.y = fmaf(vv0, w0.y, o.y);
            o.z = fmaf(vv0, w0.z, o.z); o.w = fmaf(vv0, w0.w, o.w);
            o.x = fmaf(vv1, w1.x, o.x); o.y = fmaf(vv1, w1.y, o.y);
            o.z = fmaf(vv1, w1.z, o.z); o.w = fmaf(vv1, w1.w, o.w);
            o.x = fmaf(vv2, w2.x, o.x); o.y = fmaf(vv2, w2.y, o.y);
            o.z = fmaf(vv2, w2.z, o.z); o.w = fmaf(vv2, w2.w, o.w);
            o.x = fmaf(vv3, w3.x, o.x); o.y = fmaf(vv3, w3.y, o.y);
            o.z = fmaf(vv3, w3.z, o.z); o.w = fmaf(vv3, w3.w, o.w);
        }
        o.x = fmaxf(o.x + b4.x, 0.f);
        o.y = fmaxf(o.y + b4.y, 0.f);
        o.z = fmaxf(o.z + b4.z, 0.f);
        o.w = fmaxf(o.w + b4.w, 0.f);
        ((float4*)Xout)[(size_t)node * 32 + lane] = o;
        float att = o.x * A4.x + o.y * A4.y + o.z * A4.z + o.w * A4.w;
        att += __shfl_xor_sync(0xffffffffu, att, 1);
        att += __shfl_xor_sync(0xffffffffu, att, 2);
        att += __shfl_xor_sync(0xffffffffu, att, 4);
        float cp = att * (o.x * pw4.x + o.y * pw4.y + o.z * pw4.z + o.w * pw4.w);
        #pragma unroll
        for (int ofs = 16; ofs > 0; ofs >>= 1)
            cp += __shfl_xor_sync(0xffffffffu, cp, ofs);
        if (lane == 0) catd[node] = cp * di;
    }
}

// Per-graph select, 1024 threads: hybrid shuffle/smem bitonic sort.
__global__ void __launch_bounds__(1024) k_select(
        const float* __restrict__ catd,
        const int* __restrict__ cnt, const int* __restrict__ csrIn,
        const float* __restrict__ psb, const float* __restrict__ Xmid,
        __half* __restrict__ XSout, float* __restrict__ r,
        int nper, int k, int accum,
        int* __restrict__ csrOut, int* __restrict__ cntOut) {
    __shared__ unsigned long long skey[1024];
    __shared__ float scd[1024];
    __shared__ int   snmap[1024];
    __shared__ int   sdeg[512];
    __shared__ float4 sred[1024];
    int g = blockIdx.x, t = threadIdx.x;
    int base = g * nper;
    if (t < nper) {
        scd[t] = catd[base + t];
        snmap[t] = -1;
    }
    __syncthreads();
    float pb = psb[0];
    if (t < nper) {
        int node = base + t;
        int deg = cnt[node];
        const int* row = csrIn + (size_t)node * MAXDEG;
        float din = rsqrtf((float)(deg + 1));
        float s2 = scd[t] * din;
        for (int j = 0; j < deg; j++) s2 += scd[row[j] - base];
        float sc = fmaf(s2, din, pb);
        skey[t] = ((unsigned long long)f2u_ord(sc) << 32) | (unsigned)(~t);
    }
    __syncthreads();
    // hybrid bitonic sort (descending): smem pair-steps for j>=32,
    // register/shuffle phases for j<=16.
    for (int ks = 2; ks <= nper; ks <<= 1) {
        for (int j = ks >> 1; j >= 32; j >>= 1) {
            int p = t;
            if (p < (nper >> 1)) {
                int i = ((p & ~(j - 1)) << 1) | (p & (j - 1));
                int ixj = i | j;
                unsigned long long ka = skey[i], kb = skey[ixj];
                bool dirUp = ((i & ks) == 0);
                if (dirUp ? (ka < kb) : (ka > kb)) { skey[i] = kb; skey[ixj] = ka; }
            }
            __syncthreads();
        }
        {   // register phase: j = min(ks/2, 16) .. 1
            unsigned long long key = (t < nper) ? skey[t] : 0ull;
            bool up = ((t & ks) == 0);
            int jstart = (ks >> 1 < 16) ? (ks >> 1) : 16;
            for (int j = jstart; j >= 1; j >>= 1) {
                unsigned long long other = shfl_xor_u64(key, j);
                bool takeMax = (up == ((t & j) == 0));
                if (takeMax ? (other > key) : (other < key)) key = other;
            }
            if (t < nper) skey[t] = key;
            __syncthreads();
        }
    }
    if (t < k) {
        unsigned long long key = skey[t];
        snmap[(int)(~(unsigned)key)] = g * k + t;
        scd[t] = tanhf(u2f_ord((unsigned)(key >> 32)));
    }
    __syncthreads();
    if (csrOut) {
        if (t < nper) {
            int nm = snmap[t];
            if (nm >= 0) {
                int node = base + t;
                int deg = cnt[node];
                const int* row = csrIn + (size_t)node * MAXDEG;
                int* orow = csrOut + (size_t)nm * MAXDEG;
                int cct = 0;
                for (int j = 0; j < deg; j++) {
                    int m2 = snmap[row[j] - base];
                    if (m2 >= 0) orow[cct++] = m2;
                }
                cntOut[nm] = cct;
                sdeg[nm - g * k] = cct;
            }
        }
        __syncthreads();
    }
    int f4 = t & 31, c = t >> 5;
    const float4* Xmid4 = (const float4*)Xmid;
    float4 mx = make_float4(-FLT_MAX, -FLT_MAX, -FLT_MAX, -FLT_MAX);
    float4 sm = make_float4(0.f, 0.f, 0.f, 0.f);
    for (int j = c; j < k; j += 32) {
        int orig = base + (int)(~(unsigned)skey[j]);
        float tv = scd[j];
        float4 v = Xmid4[(size_t)orig * 32 + f4];
        v.x *= tv; v.y *= tv; v.z *= tv; v.w *= tv;
        if (XSout) {
            float dn = rsqrtf((float)(sdeg[j] + 1));
            ((uint2*)XSout)[(size_t)(g * k + j) * 32 + f4] =
                pack_h4(v.x * dn, v.y * dn, v.z * dn, v.w * dn);
        }
        mx.x = fmaxf(mx.x, v.x); mx.y = fmaxf(mx.y, v.y);
        mx.z = fmaxf(mx.z, v.z); mx.w = fmaxf(mx.w, v.w);
        sm.x += v.x; sm.y += v.y; sm.z += v.z; sm.w += v.w;
    }
    sred[c * 32 + f4] = mx;
    __syncthreads();
    for (int st = 16; st >= 1; st >>= 1) {
        if (c < st) {
            float4 a = sred[c * 32 + f4], bb = sred[(c + st) * 32 + f4];
            sred[c * 32 + f4] = make_float4(fmaxf(a.x, bb.x), fmaxf(a.y, bb.y),
                                            fmaxf(a.z, bb.z), fmaxf(a.w, bb.w));
        }
        __syncthreads();
    }
    if (t < 32) {
        float4 o = sred[f4];
        float4* rp = (float4*)(r + g * 256) + f4;
        if (accum) {
            float4 old = *rp;
            o.x += old.x; o.y += old.y; o.z += old.z; o.w += old.w;
        }
        *rp = o;
    }
    __syncthreads();
    sred[c * 32 + f4] = sm;
    __syncthreads();
    for (int st = 16; st >= 1; st >>= 1) {
        if (c < st) {
            float4 a = sred[c * 32 + f4], bb = sred[(c + st) * 32 + f4];
            sred[c * 32 + f4] = make_float4(a.x + bb.x, a.y + bb.y,
                                            a.z + bb.z, a.w + bb.w);
        }
        __syncthreads();
    }
    if (t < 32) {
        float4 o = sred[f4];
        float inv = 1.0f / (float)k;
        o.x *= inv; o.y *= inv; o.z *= inv; o.w *= inv;
        float4* rp = (float4*)(r + g * 256 + 128) + f4;
        if (accum) {
            float4 old = *rp;
            o.x += old.x; o.y += old.y; o.z += old.z; o.w += old.w;
        }
        *rp = o;
    }
}

__global__ void k_mlp(const float* __restrict__ r,
                      const float* __restrict__ l1W, const float* __restrict__ l1b,
                      const float* __restrict__ l2W, const float* __restrict__ l2b,
                      const float* __restrict__ l3W, const float* __restrict__ l3b,
                      float* __restrict__ out, int* __restrict__ cnt0z) {
    __shared__ float z0[256], z1[128], z2[64], z3[16];
    __shared__ float red2[2];
    int g = blockIdx.x, t = threadIdx.x;
    z0[t] = r[g * 256 + t];
    z0[t + 128] = r[g * 256 + 128 + t];
    __syncthreads();
    {
        float acc = l1b[t];
        for (int i = 0; i < 256; i++) acc = fmaf(z0[i], l1W[i * 128 + t], acc);
        z1[t] = fmaxf(acc, 0.f);
    }
    __syncthreads();
    if (t < 64) {
        float acc = l2b[t];
        for (int i = 0; i < 128; i++) acc = fmaf(z1[i], l2W[i * 64 + t], acc);
        z2[t] = fmaxf(acc, 0.f);
    }
    __syncthreads();
    if (t < NC) {
        float acc = l3b[t];
        for (int i = 0; i < 64; i++) acc = fmaf(z2[i], l3W[i * NC + t], acc);
        z3[t] = acc;
    }
    __syncthreads();
    if (t == 0) {
        float m = -FLT_MAX;
        for (int c = 0; c < NC; c++) m = fmaxf(m, z3[c]);
        float s = 0.f;
        for (int c = 0; c < NC; c++) s += expf(z3[c] - m);
        red2[0] = m; red2[1] = logf(s);
    }
    __syncthreads();
    if (t < NC) out[g * NC + t] = z3[t] - red2[0] - red2[1];
    for (int i = g * 128 + t; i < N0; i += BGR * 128) cnt0z[i] = 0;
}

// ---------------- host side ----------------
extern "C" void kernel_launch(void* const* d_in, const int* in_sizes, int n_in,
                              void* d_out, int out_size) {
    const float* x   = (const float*)d_in[0];
    const int*   src = (const int*)d_in[1];
    const int*   dst = (const int*)d_in[2];
    const float* W1 = (const float*)d_in[3];
    const float* b1 = (const float*)d_in[4];
    const float* A1 = (const float*)d_in[5];
    const float* ps1W = (const float*)d_in[6];
    const float* ps1b = (const float*)d_in[7];
    const float* W2 = (const float*)d_in[8];
    const float* b2 = (const float*)d_in[9];
    const float* A2 = (const float*)d_in[10];
    const float* ps2W = (const float*)d_in[11];
    const float* ps2b = (const float*)d_in[12];
    const float* W3 = (const float*)d_in[13];
    const float* b3 = (const float*)d_in[14];
    const float* A3 = (const float*)d_in[15];
    const float* ps3W = (const float*)d_in[16];
    const float* ps3b = (const float*)d_in[17];
    const float* l1W = (const float*)d_in[18];
    const float* l1b = (const float*)d_in[19];
    const float* l2W = (const float*)d_in[20];
    const float* l2b = (const float*)d_in[21];
    const float* l3W = (const float*)d_in[22];
    const float* l3b = (const float*)d_in[23];
    float* out = (float*)d_out;

    float *X, *catd, *r;
    __half *XS;
    int *cnt0, *cnt1, *cnt2, *csrA, *csrB;
    cudaGetSymbolAddress((void**)&X, g_X);
    cudaGetSymbolAddress((void**)&XS, g_XS);
    cudaGetSymbolAddress((void**)&catd, g_catd);
    cudaGetSymbolAddress((void**)&r, g_r);
    cudaGetSymbolAddress((void**)&cnt0, g_cnt0);
    cudaGetSymbolAddress((void**)&cnt1, g_cnt1);
    cudaGetSymbolAddress((void**)&cnt2, g_cnt2);
    cudaGetSymbolAddress((void**)&csrA, g_csrA);
    cudaGetSymbolAddress((void**)&csrB, g_csrB);

    k_build<<<ceil_div(NE / 4, 256), 256>>>(src, dst, cnt0, csrA);

    // stage 1
    k_scale<<<ceil_div(N0 * 32, 256), 256>>>(x, cnt0, XS, N0);
    k_aggXP<<<ceil_div(N0, NPB3), 256>>>(XS, cnt0, csrA,
                                         W1, b1, A1, ps1W, X, catd, N0);
    k_select<<<BGR, 1024>>>(catd, cnt0, csrA, ps1b, X,
                            XS, r, NPER0, KK1, 0, csrB, cnt1);
    // stage 2
    k_aggXP<<<ceil_div(N1, NPB3), 256>>>(XS, cnt1, csrB,
                                         W2, b2, A2, ps2W, X, catd, N1);
    k_select<<<BGR, 1024>>>(catd, cnt1, csrB, ps2b, X,
                            XS, r, KK1, KK2, 1, csrA, cnt2);
    // stage 3
    k_aggXP<<<ceil_div(N2, NPB3), 256>>>(XS, cnt2, csrA,
                                         W3, b3, A3, ps3W, X, catd, N2);
    k_select<<<BGR, 1024>>>(catd, cnt2, csrA, ps3b, X,
                            nullptr, r, KK2, KK3, 1, nullptr, nullptr);

    k_mlp<<<BGR, 128>>>(r, l1W, l1b, l2W, l2b, l3W, l3b, out, cnt0);
}